// round 2
// baseline (speedup 1.0000x reference)
#include <cuda_runtime.h>
#include <cuda_bf16.h>
#include <math.h>

// Problem constants
#define BATCH 4
#define SEQ   1024
#define CDIM  2048
#define NHEAD 16
#define HDIM  128
#define C3    (3*CDIM)
#define MROWS (BATCH*SEQ)      // 4096
#define BHTOT (BATCH*NHEAD)    // 64

// Scratch (allocation-free rule: __device__ globals)
__device__ float g_qkv[(size_t)MROWS * C3];          // [4096][6144]
__device__ float g_q  [(size_t)BHTOT * SEQ * HDIM];  // [64][1024][128]
__device__ float g_k  [(size_t)BHTOT * SEQ * HDIM];
__device__ float g_v  [(size_t)BHTOT * SEQ * HDIM];
__device__ float g_y  [(size_t)MROWS * CDIM];        // [4096][2048]
__device__ float g_cos[SEQ * 64];
__device__ float g_sin[SEQ * 64];

// ---------------------------------------------------------------------------
// RoPE tables (double precision to avoid fast-math angle error at t*invf ~ 1e3)
// ---------------------------------------------------------------------------
__global__ void build_rope_kernel(float* __restrict__ ct, float* __restrict__ st) {
    int idx = blockIdx.x * blockDim.x + threadIdx.x;
    if (idx >= SEQ * 64) return;
    int t = idx >> 6;
    int i = idx & 63;
    double invf = pow(10000.0, -(double)i / 64.0);
    double ang  = (double)t * invf;
    ct[idx] = (float)cos(ang);
    st[idx] = (float)sin(ang);
}

// ---------------------------------------------------------------------------
// fp32 SGEMM: C[M,N] = A[M,K] @ B[K,N] + bias[N]
// 128x128 block tile, BK=16, 256 threads, 8x8 per-thread
// ---------------------------------------------------------------------------
__global__ __launch_bounds__(256, 2)
void sgemm_bias_kernel(const float* __restrict__ A, const float* __restrict__ B,
                       const float* __restrict__ bias, float* __restrict__ C,
                       int M, int N, int K) {
    constexpr int BM = 128, BN = 128, BK = 16;
    __shared__ float As[BK][BM];
    __shared__ float Bs[BK][BN];

    int tid = threadIdx.x;
    int tx = tid & 15;          // 0..15 -> N
    int ty = tid >> 4;          // 0..15 -> M
    int bm = blockIdx.y * BM;
    int bn = blockIdx.x * BN;

    int arow  = tid >> 2;       // 0..63
    int acol4 = tid & 3;        // 0..3  (k in float4 units)
    int brow  = tid >> 5;       // 0..7
    int bcol4 = tid & 31;       // 0..31 (n in float4 units)

    float acc[8][8];
    #pragma unroll
    for (int i = 0; i < 8; i++)
        #pragma unroll
        for (int j = 0; j < 8; j++) acc[i][j] = 0.f;

    for (int k0 = 0; k0 < K; k0 += BK) {
        #pragma unroll
        for (int r = 0; r < 2; r++) {
            int row = arow + r * 64;
            float4 a = *(const float4*)(A + (size_t)(bm + row) * K + k0 + acol4 * 4);
            As[acol4*4+0][row] = a.x;
            As[acol4*4+1][row] = a.y;
            As[acol4*4+2][row] = a.z;
            As[acol4*4+3][row] = a.w;
        }
        #pragma unroll
        for (int r = 0; r < 2; r++) {
            int row = brow + r * 8;
            *(float4*)(&Bs[row][bcol4*4]) =
                *(const float4*)(B + (size_t)(k0 + row) * N + bn + bcol4 * 4);
        }
        __syncthreads();

        #pragma unroll
        for (int k = 0; k < BK; k++) {
            float ra[8], rb[8];
            float4 a0 = *(float4*)(&As[k][ty*8]);
            float4 a1 = *(float4*)(&As[k][ty*8+4]);
            float4 b0 = *(float4*)(&Bs[k][tx*8]);
            float4 b1 = *(float4*)(&Bs[k][tx*8+4]);
            ra[0]=a0.x; ra[1]=a0.y; ra[2]=a0.z; ra[3]=a0.w;
            ra[4]=a1.x; ra[5]=a1.y; ra[6]=a1.z; ra[7]=a1.w;
            rb[0]=b0.x; rb[1]=b0.y; rb[2]=b0.z; rb[3]=b0.w;
            rb[4]=b1.x; rb[5]=b1.y; rb[6]=b1.z; rb[7]=b1.w;
            #pragma unroll
            for (int i = 0; i < 8; i++)
                #pragma unroll
                for (int j = 0; j < 8; j++)
                    acc[i][j] = fmaf(ra[i], rb[j], acc[i][j]);
        }
        __syncthreads();
    }

    #pragma unroll
    for (int i = 0; i < 8; i++) {
        int row = bm + ty * 8 + i;
        #pragma unroll
        for (int j = 0; j < 8; j += 4) {
            int col = bn + tx * 8 + j;
            float4 v;
            v.x = acc[i][j+0] + bias[col+0];
            v.y = acc[i][j+1] + bias[col+1];
            v.z = acc[i][j+2] + bias[col+2];
            v.w = acc[i][j+3] + bias[col+3];
            *(float4*)(C + (size_t)row * N + col) = v;
        }
    }
}

// ---------------------------------------------------------------------------
// RoPE + scatter: qkv [B,T,3,H,D] -> q,k (roped), v in [B*H, T, D]
// ---------------------------------------------------------------------------
__global__ void rope_scatter_kernel(const float* __restrict__ qkv,
                                    const float* __restrict__ ct,
                                    const float* __restrict__ st,
                                    float* __restrict__ q,
                                    float* __restrict__ k,
                                    float* __restrict__ v) {
    int idx = blockIdx.x * blockDim.x + threadIdx.x;
    if (idx >= BHTOT * SEQ * HDIM) return;
    int d  = idx & 127;
    int t  = (idx >> 7) & 1023;
    int bh = idx >> 17;
    int b  = bh >> 4;
    int h  = bh & 15;

    size_t base = (size_t)(b * SEQ + t) * C3 + h * HDIM;
    v[idx] = qkv[base + 2 * CDIM + d];

    int i = d & 63;
    float c = ct[t * 64 + i];
    float s = st[t * 64 + i];
    float q1 = qkv[base + i];
    float q2 = qkv[base + i + 64];
    float k1 = qkv[base + CDIM + i];
    float k2 = qkv[base + CDIM + i + 64];
    float qo, ko;
    if (d < 64) { qo = q1 * c - q2 * s; ko = k1 * c - k2 * s; }
    else        { qo = q1 * s + q2 * c; ko = k1 * s + k2 * c; }
    q[idx] = qo;
    k[idx] = ko;
}

// ---------------------------------------------------------------------------
// Flash attention (fp32), causal. One CTA = 64 q rows for one (b,h).
// 256 threads: tx (0..15) -> cols, ty (0..15) -> rows (4 rows each).
// ---------------------------------------------------------------------------
__global__ __launch_bounds__(256, 1)
void flash_attn_kernel(const float* __restrict__ Q, const float* __restrict__ K,
                       const float* __restrict__ V, float* __restrict__ Y) {
    extern __shared__ float sm[];
    float* Qs = sm;                    // [128][64]  d-major
    float* Ks = Qs + 128 * 64;         // [128][64]  d-major
    float* Vs = Ks + 128 * 64;         // [64][128]  row-major
    float* Ps = Vs + 64 * 128;         // [64][64]

    int tid = threadIdx.x;
    int tx = tid & 15;
    int ty = tid >> 4;
    int qt = blockIdx.x;
    int bh = blockIdx.y;
    int q0 = qt * 64;
    int b = bh >> 4, h = bh & 15;
    const float scale = 0.08838834764831845f;  // 1/sqrt(128)

    // load Q tile transposed, pre-scaled
    const float* Qg = Q + ((size_t)bh * SEQ + q0) * HDIM;
    #pragma unroll
    for (int i = 0; i < 8; i++) {
        int idx = tid + i * 256;     // 0..2047
        int r = idx >> 5;            // 0..63
        int c4 = idx & 31;           // float4 idx in D
        float4 qv = *(const float4*)(Qg + (size_t)r * HDIM + c4 * 4);
        Qs[(c4*4+0)*64 + r] = qv.x * scale;
        Qs[(c4*4+1)*64 + r] = qv.y * scale;
        Qs[(c4*4+2)*64 + r] = qv.z * scale;
        Qs[(c4*4+3)*64 + r] = qv.w * scale;
    }

    float o[4][8];
    float m[4], l[4];
    #pragma unroll
    for (int i = 0; i < 4; i++) {
        m[i] = -1e30f; l[i] = 0.f;
        #pragma unroll
        for (int j = 0; j < 8; j++) o[i][j] = 0.f;
    }

    int nkt = qt + 1;
    for (int kt = 0; kt < nkt; kt++) {
        int k0 = kt * 64;
        const float* Kg = K + ((size_t)bh * SEQ + k0) * HDIM;
        const float* Vg = V + ((size_t)bh * SEQ + k0) * HDIM;
        __syncthreads();   // prev PV read done (and Q store visible on first iter)
        #pragma unroll
        for (int i = 0; i < 8; i++) {
            int idx = tid + i * 256;
            int r = idx >> 5, c4 = idx & 31;
            float4 kv = *(const float4*)(Kg + (size_t)r * HDIM + c4 * 4);
            Ks[(c4*4+0)*64 + r] = kv.x;
            Ks[(c4*4+1)*64 + r] = kv.y;
            Ks[(c4*4+2)*64 + r] = kv.z;
            Ks[(c4*4+3)*64 + r] = kv.w;
            *(float4*)(Vs + (size_t)r * 128 + c4 * 4) =
                *(const float4*)(Vg + (size_t)r * HDIM + c4 * 4);
        }
        __syncthreads();

        // S = (scaled Q) @ K^T  : s[i][j], row q0+ty*4+i, col k0+tx*4+j
        float s[4][4];
        #pragma unroll
        for (int i = 0; i < 4; i++)
            #pragma unroll
            for (int j = 0; j < 4; j++) s[i][j] = 0.f;
        #pragma unroll 4
        for (int d = 0; d < 128; d++) {
            float4 qv = *(float4*)(Qs + d * 64 + ty * 4);
            float4 kv = *(float4*)(Ks + d * 64 + tx * 4);
            float ra[4] = {qv.x, qv.y, qv.z, qv.w};
            float rb[4] = {kv.x, kv.y, kv.z, kv.w};
            #pragma unroll
            for (int i = 0; i < 4; i++)
                #pragma unroll
                for (int j = 0; j < 4; j++)
                    s[i][j] = fmaf(ra[i], rb[j], s[i][j]);
        }

        // causal mask on the diagonal tile
        if (kt == qt) {
            #pragma unroll
            for (int i = 0; i < 4; i++) {
                int r = ty * 4 + i;
                #pragma unroll
                for (int j = 0; j < 4; j++) {
                    int c = tx * 4 + j;
                    if (c > r) s[i][j] = -1e30f;
                }
            }
        }

        // online softmax
        #pragma unroll
        for (int i = 0; i < 4; i++) {
            float tmax = fmaxf(fmaxf(s[i][0], s[i][1]), fmaxf(s[i][2], s[i][3]));
            #pragma unroll
            for (int off = 8; off >= 1; off >>= 1)
                tmax = fmaxf(tmax, __shfl_xor_sync(0xffffffffu, tmax, off));
            float mnew = fmaxf(m[i], tmax);
            float p0 = __expf(s[i][0] - mnew);
            float p1 = __expf(s[i][1] - mnew);
            float p2 = __expf(s[i][2] - mnew);
            float p3 = __expf(s[i][3] - mnew);
            float rs = p0 + p1 + p2 + p3;
            #pragma unroll
            for (int off = 8; off >= 1; off >>= 1)
                rs += __shfl_xor_sync(0xffffffffu, rs, off);
            float alpha = __expf(m[i] - mnew);
            l[i] = l[i] * alpha + rs;
            m[i] = mnew;
            #pragma unroll
            for (int j = 0; j < 8; j++) o[i][j] *= alpha;
            int rr = ty * 4 + i;
            Ps[rr * 64 + tx * 4 + 0] = p0;
            Ps[rr * 64 + tx * 4 + 1] = p1;
            Ps[rr * 64 + tx * 4 + 2] = p2;
            Ps[rr * 64 + tx * 4 + 3] = p3;
        }
        __syncthreads();

        // O += P @ V
        #pragma unroll 4
        for (int j = 0; j < 64; j++) {
            float p0 = Ps[(ty*4+0) * 64 + j];
            float p1 = Ps[(ty*4+1) * 64 + j];
            float p2 = Ps[(ty*4+2) * 64 + j];
            float p3 = Ps[(ty*4+3) * 64 + j];
            float4 v0 = *(float4*)(Vs + j * 128 + tx * 8);
            float4 v1 = *(float4*)(Vs + j * 128 + tx * 8 + 4);
            float vv[8] = {v0.x, v0.y, v0.z, v0.w, v1.x, v1.y, v1.z, v1.w};
            #pragma unroll
            for (int d = 0; d < 8; d++) {
                o[0][d] = fmaf(p0, vv[d], o[0][d]);
                o[1][d] = fmaf(p1, vv[d], o[1][d]);
                o[2][d] = fmaf(p2, vv[d], o[2][d]);
                o[3][d] = fmaf(p3, vv[d], o[3][d]);
            }
        }
    }

    // epilogue: normalize + write to y [B,T,H,D] == [B,T,C]
    #pragma unroll
    for (int i = 0; i < 4; i++) {
        float inv = 1.0f / l[i];
        int t = q0 + ty * 4 + i;
        size_t off = (size_t)(b * SEQ + t) * CDIM + h * HDIM + tx * 8;
        float4 r0, r1;
        r0.x = o[i][0]*inv; r0.y = o[i][1]*inv; r0.z = o[i][2]*inv; r0.w = o[i][3]*inv;
        r1.x = o[i][4]*inv; r1.y = o[i][5]*inv; r1.z = o[i][6]*inv; r1.w = o[i][7]*inv;
        *(float4*)(Y + off)     = r0;
        *(float4*)(Y + off + 4) = r1;
    }
}

// ---------------------------------------------------------------------------
extern "C" void kernel_launch(void* const* d_in, const int* in_sizes, int n_in,
                              void* d_out, int out_size) {
    const float* x      = (const float*)d_in[0];
    const float* w_attn = (const float*)d_in[1];
    const float* b_attn = (const float*)d_in[2];
    const float* w_proj = (const float*)d_in[3];
    const float* b_proj = (const float*)d_in[4];
    float* out = (float*)d_out;

    float *qkv, *q, *k, *v, *y, *ct, *st;
    cudaGetSymbolAddress((void**)&qkv, g_qkv);
    cudaGetSymbolAddress((void**)&q,   g_q);
    cudaGetSymbolAddress((void**)&k,   g_k);
    cudaGetSymbolAddress((void**)&v,   g_v);
    cudaGetSymbolAddress((void**)&y,   g_y);
    cudaGetSymbolAddress((void**)&ct,  g_cos);
    cudaGetSymbolAddress((void**)&st,  g_sin);

    // RoPE tables
    build_rope_kernel<<<(SEQ * 64 + 255) / 256, 256>>>(ct, st);

    // QKV projection: [4096,2048] @ [2048,6144] + bias
    sgemm_bias_kernel<<<dim3(C3 / 128, MROWS / 128), 256>>>(
        x, w_attn, b_attn, qkv, MROWS, C3, CDIM);

    // RoPE + scatter into [B*H, T, D]
    rope_scatter_kernel<<<(BHTOT * SEQ * HDIM + 255) / 256, 256>>>(qkv, ct, st, q, k, v);

    // Flash attention
    static const size_t smem_bytes = (128*64 + 128*64 + 64*128 + 64*64) * sizeof(float);
    cudaFuncSetAttribute(flash_attn_kernel,
                         cudaFuncAttributeMaxDynamicSharedMemorySize, (int)smem_bytes);
    flash_attn_kernel<<<dim3(SEQ / 64, BHTOT), 256, smem_bytes>>>(q, k, v, y);

    // Output projection: [4096,2048] @ [2048,2048] + bias -> d_out
    sgemm_bias_kernel<<<dim3(CDIM / 128, MROWS / 128), 256>>>(
        y, w_proj, b_proj, out, MROWS, CDIM, CDIM);
}

// round 4
// speedup vs baseline: 1.9851x; 1.9851x over previous
#include <cuda_runtime.h>
#include <cuda_bf16.h>
#include <math.h>
#include <stdint.h>

// Problem constants
#define BATCH 4
#define SEQ   1024
#define CDIM  2048
#define NHEAD 16
#define HDIM  128
#define C3    (3*CDIM)
#define MROWS (BATCH*SEQ)      // 4096
#define BHTOT (BATCH*NHEAD)    // 64
#define KW    6144             // split K' = 3*2048 (both GEMMs)
#define NKITER 96              // KW / 64

// ---------------------------------------------------------------------------
// Scratch (__device__ globals; allocation-free rule)
// ---------------------------------------------------------------------------
__device__ float g_qkv[(size_t)MROWS * C3];
__device__ float g_q  [(size_t)BHTOT * SEQ * HDIM];
__device__ float g_k  [(size_t)BHTOT * SEQ * HDIM];
__device__ float g_v  [(size_t)BHTOT * SEQ * HDIM];
__device__ float g_y  [(size_t)MROWS * CDIM];
__device__ float g_cos[SEQ * 64];
__device__ float g_sin[SEQ * 64];
__device__ __nv_bfloat16 g_Abuf[(size_t)MROWS * KW];  // A'' [4096][6144]
__device__ __nv_bfloat16 g_Bt1 [(size_t)C3 * KW];     // w_attn^T'' [6144][6144]
__device__ __nv_bfloat16 g_Bt2 [(size_t)CDIM * KW];   // w_proj^T'' [2048][6144]

// ---------------------------------------------------------------------------
// PTX helpers (arch-neutral: sm_80+ only — NO tcgen05, harness targets compute_103)
// ---------------------------------------------------------------------------
__device__ __forceinline__ uint32_t smem_u32(const void* p) {
    uint32_t a;
    asm("{ .reg .u64 t; cvta.to.shared.u64 t, %1; cvt.u32.u64 %0, t; }" : "=r"(a) : "l"(p));
    return a;
}
#define CP_ASYNC16(dst, src) \
    asm volatile("cp.async.cg.shared.global [%0], [%1], 16;" :: "r"(dst), "l"(src))
#define CP_COMMIT() asm volatile("cp.async.commit_group;" ::: "memory")
#define CP_WAIT(n)  asm volatile("cp.async.wait_group %0;" :: "n"(n) : "memory")

__device__ __forceinline__ void ldsm_x4(uint32_t& r0, uint32_t& r1, uint32_t& r2,
                                        uint32_t& r3, uint32_t addr) {
    asm volatile("ldmatrix.sync.aligned.m8n8.x4.shared.b16 {%0,%1,%2,%3}, [%4];"
                 : "=r"(r0), "=r"(r1), "=r"(r2), "=r"(r3) : "r"(addr));
}
__device__ __forceinline__ void mma_bf16(float& d0, float& d1, float& d2, float& d3,
                                         uint32_t a0, uint32_t a1, uint32_t a2, uint32_t a3,
                                         uint32_t b0, uint32_t b1) {
    asm volatile("mma.sync.aligned.m16n8k16.row.col.f32.bf16.bf16.f32 "
                 "{%0,%1,%2,%3}, {%4,%5,%6,%7}, {%8,%9}, {%0,%1,%2,%3};"
                 : "+f"(d0), "+f"(d1), "+f"(d2), "+f"(d3)
                 : "r"(a0), "r"(a1), "r"(a2), "r"(a3), "r"(b0), "r"(b1));
}

// ---------------------------------------------------------------------------
// RoPE tables (double precision to keep angle error << 1e-3 at t*invf ~ 1e3)
// ---------------------------------------------------------------------------
__global__ void build_rope_kernel(float* __restrict__ ct, float* __restrict__ st) {
    int idx = blockIdx.x * blockDim.x + threadIdx.x;
    if (idx >= SEQ * 64) return;
    int t = idx >> 6;
    int i = idx & 63;
    double invf = pow(10000.0, -(double)i / 64.0);
    double ang  = (double)t * invf;
    ct[idx] = (float)cos(ang);
    st[idx] = (float)sin(ang);
}

// ---------------------------------------------------------------------------
// Split-bf16 conversion of activations: X fp32 [4096][2048] -> [4096][6144]
// K-blocks: [hi | hi | lo]
// ---------------------------------------------------------------------------
__global__ void convert_A_kernel(const float* __restrict__ X, __nv_bfloat16* __restrict__ out) {
    int idx = blockIdx.x * blockDim.x + threadIdx.x;
    if (idx >= MROWS * CDIM / 4) return;
    int m  = idx >> 9;              // / 512
    int c4 = idx & 511;
    float4 v = ((const float4*)X)[idx];
    __nv_bfloat16 h0 = __float2bfloat16(v.x), h1 = __float2bfloat16(v.y);
    __nv_bfloat16 h2 = __float2bfloat16(v.z), h3 = __float2bfloat16(v.w);
    __nv_bfloat16 l0 = __float2bfloat16(v.x - __bfloat162float(h0));
    __nv_bfloat16 l1 = __float2bfloat16(v.y - __bfloat162float(h1));
    __nv_bfloat16 l2 = __float2bfloat16(v.z - __bfloat162float(h2));
    __nv_bfloat16 l3 = __float2bfloat16(v.w - __bfloat162float(h3));
    ushort4 hv = { __bfloat16_as_ushort(h0), __bfloat16_as_ushort(h1),
                   __bfloat16_as_ushort(h2), __bfloat16_as_ushort(h3) };
    ushort4 lv = { __bfloat16_as_ushort(l0), __bfloat16_as_ushort(l1),
                   __bfloat16_as_ushort(l2), __bfloat16_as_ushort(l3) };
    size_t ro = (size_t)m * KW + c4 * 4;
    *(ushort4*)((unsigned short*)out + ro)            = hv;
    *(ushort4*)((unsigned short*)out + ro + CDIM)     = hv;
    *(ushort4*)((unsigned short*)out + ro + 2 * CDIM) = lv;
}

// ---------------------------------------------------------------------------
// Split-bf16 + transpose of weights: W fp32 [2048][N] -> out bf16 [N][6144]
// K-blocks: [hi | lo | hi]
// ---------------------------------------------------------------------------
__global__ void convert_Bt_kernel(const float* __restrict__ W, __nv_bfloat16* __restrict__ out,
                                  int N) {
    __shared__ float t[32][33];
    int k0 = blockIdx.x * 32, n0 = blockIdx.y * 32;
    int tx = threadIdx.x, ty = threadIdx.y;   // (32, 8)
    #pragma unroll
    for (int r = 0; r < 32; r += 8)
        t[ty + r][tx] = W[(size_t)(k0 + ty + r) * N + n0 + tx];
    __syncthreads();
    #pragma unroll
    for (int r = 0; r < 32; r += 8) {
        int n = n0 + ty + r;
        int k = k0 + tx;
        float v = t[tx][ty + r];
        __nv_bfloat16 hi = __float2bfloat16(v);
        __nv_bfloat16 lo = __float2bfloat16(v - __bfloat162float(hi));
        size_t ro = (size_t)n * KW;
        out[ro + k]            = hi;
        out[ro + CDIM + k]     = lo;
        out[ro + 2 * CDIM + k] = hi;
    }
}

// ---------------------------------------------------------------------------
// mma.sync bf16 GEMM: C[M,N] = A''[M,6144] @ Bt''[N,6144]^T + bias
// CTA tile 128x128, BK=64, 3-stage cp.async ring, 8 warps (4M x 2N),
// warp tile 32x64, m16n8k16 HMMA, SW128-swizzled smem + ldmatrix.x4.
// ---------------------------------------------------------------------------
#define STAGES 3
#define STAGE_BYTES (32 * 1024)
#define GEMM_SMEM (STAGES * STAGE_BYTES + 1024)

__global__ __launch_bounds__(256, 2)
void mma_gemm_kernel(const __nv_bfloat16* __restrict__ A,
                     const __nv_bfloat16* __restrict__ Bt,
                     const float* __restrict__ bias,
                     float* __restrict__ C, int N) {
    extern __shared__ char smem_raw[];
    uint32_t smem_base = (smem_u32(smem_raw) + 1023u) & ~1023u;

    int tid  = threadIdx.x;
    int wid  = tid >> 5, lane = tid & 31;
    int wm   = wid >> 1;          // 0..3  (M)
    int wn   = wid & 1;           // 0..1  (N)

    int n0 = blockIdx.x * 128;
    int m0 = blockIdx.y * 128;

    const __nv_bfloat16* Ag0 = A  + (size_t)m0 * KW;
    const __nv_bfloat16* Bg0 = Bt + (size_t)n0 * KW;

    // ---- per-thread cp.async fill coordinates (8 chunks A + 8 chunks B) ----
    // chunk ch in [0,1024): row = ch>>3 (0..127), col16 = ch&7; SW128 swizzle.
    // ---- per-thread ldmatrix base offsets ----
    uint32_t a_off[2], a_xor[2];
    #pragma unroll
    for (int mi = 0; mi < 2; mi++) {
        int row = wm * 32 + mi * 16 + (lane & 15);
        a_off[mi] = (uint32_t)row * 128u;
        a_xor[mi] = (uint32_t)((row & 7) << 4);
    }
    uint32_t a_kb = (uint32_t)((lane >> 4) * 16);
    uint32_t b_off[4], b_xor[4];
    #pragma unroll
    for (int ng = 0; ng < 4; ng++) {
        int row = wn * 64 + ng * 16 + ((lane >> 4) << 3) + (lane & 7);
        b_off[ng] = 16384u + (uint32_t)row * 128u;
        b_xor[ng] = (uint32_t)((row & 7) << 4);
    }
    uint32_t b_kb = (uint32_t)(((lane >> 3) & 1) * 16);

    float d[2][8][4];
    #pragma unroll
    for (int mi = 0; mi < 2; mi++)
        #pragma unroll
        for (int ni = 0; ni < 8; ni++)
            #pragma unroll
            for (int c = 0; c < 4; c++) d[mi][ni][c] = 0.f;

    auto fill = [&](int s, int i) {
        int k0 = i * 64;
        uint32_t st_base = smem_base + s * STAGE_BYTES;
        const __nv_bfloat16* Ag = Ag0 + k0;
        #pragma unroll
        for (int j = 0; j < 4; j++) {
            int ch  = j * 256 + tid;           // 0..1023
            int row = ch >> 3, col = ch & 7;
            uint32_t off = (uint32_t)row * 128u + (uint32_t)col * 16u;
            uint32_t dst = st_base + (off ^ ((off >> 3) & 0x70u));
            CP_ASYNC16(dst, Ag + (size_t)row * KW + col * 8);
        }
        const __nv_bfloat16* Bg = Bg0 + k0;
        #pragma unroll
        for (int j = 0; j < 4; j++) {
            int ch  = j * 256 + tid;
            int row = ch >> 3, col = ch & 7;
            uint32_t off = (uint32_t)row * 128u + (uint32_t)col * 16u;
            uint32_t dst = st_base + 16384u + (off ^ ((off >> 3) & 0x70u));
            CP_ASYNC16(dst, Bg + (size_t)row * KW + col * 8);
        }
    };

    fill(0, 0); CP_COMMIT();
    fill(1, 1); CP_COMMIT();

    for (int i = 0; i < NKITER; i++) {
        int s = i % STAGES;
        CP_WAIT(1);
        __syncthreads();

        uint32_t stb = smem_base + s * STAGE_BYTES;
        #pragma unroll
        for (int ks = 0; ks < 4; ks++) {
            uint32_t kk = (uint32_t)(ks * 32);
            uint32_t af[2][4];
            #pragma unroll
            for (int mi = 0; mi < 2; mi++) {
                uint32_t addr = stb + a_off[mi] + ((kk + a_kb) ^ a_xor[mi]);
                ldsm_x4(af[mi][0], af[mi][1], af[mi][2], af[mi][3], addr);
            }
            uint32_t bf[4][4];
            #pragma unroll
            for (int ng = 0; ng < 4; ng++) {
                uint32_t addr = stb + b_off[ng] + ((kk + b_kb) ^ b_xor[ng]);
                ldsm_x4(bf[ng][0], bf[ng][1], bf[ng][2], bf[ng][3], addr);
            }
            #pragma unroll
            for (int mi = 0; mi < 2; mi++)
                #pragma unroll
                for (int ni = 0; ni < 8; ni++) {
                    int ng = ni >> 1, sub = ni & 1;
                    mma_bf16(d[mi][ni][0], d[mi][ni][1], d[mi][ni][2], d[mi][ni][3],
                             af[mi][0], af[mi][1], af[mi][2], af[mi][3],
                             bf[ng][sub * 2], bf[ng][sub * 2 + 1]);
                }
        }
        __syncthreads();
        if (i + 2 < NKITER) fill((i + 2) % STAGES, i + 2);
        CP_COMMIT();
    }
    CP_WAIT(0);

    // ---- epilogue: add bias, store fp32 ----
    int row_base = m0 + wm * 32 + (lane >> 2);
    int col_base = n0 + wn * 64 + (lane & 3) * 2;
    #pragma unroll
    for (int ni = 0; ni < 8; ni++) {
        int col = col_base + ni * 8;
        float2 bs = *(const float2*)(bias + col);
        #pragma unroll
        for (int mi = 0; mi < 2; mi++) {
            int r0 = row_base + mi * 16;
            float2 v0 = { d[mi][ni][0] + bs.x, d[mi][ni][1] + bs.y };
            float2 v1 = { d[mi][ni][2] + bs.x, d[mi][ni][3] + bs.y };
            *(float2*)(C + (size_t)r0 * N + col)       = v0;
            *(float2*)(C + (size_t)(r0 + 8) * N + col) = v1;
        }
    }
}

// ---------------------------------------------------------------------------
// RoPE + scatter: qkv [B,T,3,H,D] -> q,k (roped), v in [B*H, T, D]
// ---------------------------------------------------------------------------
__global__ void rope_scatter_kernel(const float* __restrict__ qkv,
                                    const float* __restrict__ ct,
                                    const float* __restrict__ st,
                                    float* __restrict__ q,
                                    float* __restrict__ k,
                                    float* __restrict__ v) {
    int idx = blockIdx.x * blockDim.x + threadIdx.x;
    if (idx >= BHTOT * SEQ * HDIM) return;
    int d  = idx & 127;
    int t  = (idx >> 7) & 1023;
    int bh = idx >> 17;
    int b  = bh >> 4;
    int h  = bh & 15;

    size_t base = (size_t)(b * SEQ + t) * C3 + h * HDIM;
    v[idx] = qkv[base + 2 * CDIM + d];

    int i = d & 63;
    float c = ct[t * 64 + i];
    float s = st[t * 64 + i];
    float q1 = qkv[base + i];
    float q2 = qkv[base + i + 64];
    float k1 = qkv[base + CDIM + i];
    float k2 = qkv[base + CDIM + i + 64];
    float qo, ko;
    if (d < 64) { qo = q1 * c - q2 * s; ko = k1 * c - k2 * s; }
    else        { qo = q1 * s + q2 * c; ko = k1 * s + k2 * c; }
    q[idx] = qo;
    k[idx] = ko;
}

// ---------------------------------------------------------------------------
// Flash attention (fp32), causal. One CTA = 64 q rows for one (b,h).
// ---------------------------------------------------------------------------
__global__ __launch_bounds__(256, 1)
void flash_attn_kernel(const float* __restrict__ Q, const float* __restrict__ K,
                       const float* __restrict__ V, float* __restrict__ Y) {
    extern __shared__ float sm[];
    float* Qs = sm;                    // [128][64]  d-major
    float* Ks = Qs + 128 * 64;         // [128][64]  d-major
    float* Vs = Ks + 128 * 64;         // [64][128]  row-major
    float* Ps = Vs + 64 * 128;         // [64][64]

    int tid = threadIdx.x;
    int tx = tid & 15;
    int ty = tid >> 4;
    int qt = blockIdx.x;
    int bh = blockIdx.y;
    int q0 = qt * 64;
    int b = bh >> 4, h = bh & 15;
    const float scale = 0.08838834764831845f;  // 1/sqrt(128)

    const float* Qg = Q + ((size_t)bh * SEQ + q0) * HDIM;
    #pragma unroll
    for (int i = 0; i < 8; i++) {
        int idx = tid + i * 256;
        int r = idx >> 5;
        int c4 = idx & 31;
        float4 qv = *(const float4*)(Qg + (size_t)r * HDIM + c4 * 4);
        Qs[(c4*4+0)*64 + r] = qv.x * scale;
        Qs[(c4*4+1)*64 + r] = qv.y * scale;
        Qs[(c4*4+2)*64 + r] = qv.z * scale;
        Qs[(c4*4+3)*64 + r] = qv.w * scale;
    }

    float o[4][8];
    float m[4], l[4];
    #pragma unroll
    for (int i = 0; i < 4; i++) {
        m[i] = -1e30f; l[i] = 0.f;
        #pragma unroll
        for (int j = 0; j < 8; j++) o[i][j] = 0.f;
    }

    int nkt = qt + 1;
    for (int kt = 0; kt < nkt; kt++) {
        int k0 = kt * 64;
        const float* Kg = K + ((size_t)bh * SEQ + k0) * HDIM;
        const float* Vg = V + ((size_t)bh * SEQ + k0) * HDIM;
        __syncthreads();
        #pragma unroll
        for (int i = 0; i < 8; i++) {
            int idx = tid + i * 256;
            int r = idx >> 5, c4 = idx & 31;
            float4 kv = *(const float4*)(Kg + (size_t)r * HDIM + c4 * 4);
            Ks[(c4*4+0)*64 + r] = kv.x;
            Ks[(c4*4+1)*64 + r] = kv.y;
            Ks[(c4*4+2)*64 + r] = kv.z;
            Ks[(c4*4+3)*64 + r] = kv.w;
            *(float4*)(Vs + (size_t)r * 128 + c4 * 4) =
                *(const float4*)(Vg + (size_t)r * HDIM + c4 * 4);
        }
        __syncthreads();

        float s[4][4];
        #pragma unroll
        for (int i = 0; i < 4; i++)
            #pragma unroll
            for (int j = 0; j < 4; j++) s[i][j] = 0.f;
        #pragma unroll 4
        for (int d = 0; d < 128; d++) {
            float4 qv = *(float4*)(Qs + d * 64 + ty * 4);
            float4 kv = *(float4*)(Ks + d * 64 + tx * 4);
            float ra[4] = {qv.x, qv.y, qv.z, qv.w};
            float rb[4] = {kv.x, kv.y, kv.z, kv.w};
            #pragma unroll
            for (int i = 0; i < 4; i++)
                #pragma unroll
                for (int j = 0; j < 4; j++)
                    s[i][j] = fmaf(ra[i], rb[j], s[i][j]);
        }

        if (kt == qt) {
            #pragma unroll
            for (int i = 0; i < 4; i++) {
                int r = ty * 4 + i;
                #pragma unroll
                for (int j = 0; j < 4; j++) {
                    int c = tx * 4 + j;
                    if (c > r) s[i][j] = -1e30f;
                }
            }
        }

        #pragma unroll
        for (int i = 0; i < 4; i++) {
            float tmax = fmaxf(fmaxf(s[i][0], s[i][1]), fmaxf(s[i][2], s[i][3]));
            #pragma unroll
            for (int off = 8; off >= 1; off >>= 1)
                tmax = fmaxf(tmax, __shfl_xor_sync(0xffffffffu, tmax, off));
            float mnew = fmaxf(m[i], tmax);
            float p0 = __expf(s[i][0] - mnew);
            float p1 = __expf(s[i][1] - mnew);
            float p2 = __expf(s[i][2] - mnew);
            float p3 = __expf(s[i][3] - mnew);
            float rs = p0 + p1 + p2 + p3;
            #pragma unroll
            for (int off = 8; off >= 1; off >>= 1)
                rs += __shfl_xor_sync(0xffffffffu, rs, off);
            float alpha = __expf(m[i] - mnew);
            l[i] = l[i] * alpha + rs;
            m[i] = mnew;
            #pragma unroll
            for (int j = 0; j < 8; j++) o[i][j] *= alpha;
            int rr = ty * 4 + i;
            Ps[rr * 64 + tx * 4 + 0] = p0;
            Ps[rr * 64 + tx * 4 + 1] = p1;
            Ps[rr * 64 + tx * 4 + 2] = p2;
            Ps[rr * 64 + tx * 4 + 3] = p3;
        }
        __syncthreads();

        #pragma unroll 4
        for (int j = 0; j < 64; j++) {
            float p0 = Ps[(ty*4+0) * 64 + j];
            float p1 = Ps[(ty*4+1) * 64 + j];
            float p2 = Ps[(ty*4+2) * 64 + j];
            float p3 = Ps[(ty*4+3) * 64 + j];
            float4 v0 = *(float4*)(Vs + j * 128 + tx * 8);
            float4 v1 = *(float4*)(Vs + j * 128 + tx * 8 + 4);
            float vv[8] = {v0.x, v0.y, v0.z, v0.w, v1.x, v1.y, v1.z, v1.w};
            #pragma unroll
            for (int d = 0; d < 8; d++) {
                o[0][d] = fmaf(p0, vv[d], o[0][d]);
                o[1][d] = fmaf(p1, vv[d], o[1][d]);
                o[2][d] = fmaf(p2, vv[d], o[2][d]);
                o[3][d] = fmaf(p3, vv[d], o[3][d]);
            }
        }
    }

    #pragma unroll
    for (int i = 0; i < 4; i++) {
        float inv = 1.0f / l[i];
        int t = q0 + ty * 4 + i;
        size_t off = (size_t)(b * SEQ + t) * CDIM + h * HDIM + tx * 8;
        float4 r0, r1;
        r0.x = o[i][0]*inv; r0.y = o[i][1]*inv; r0.z = o[i][2]*inv; r0.w = o[i][3]*inv;
        r1.x = o[i][4]*inv; r1.y = o[i][5]*inv; r1.z = o[i][6]*inv; r1.w = o[i][7]*inv;
        *(float4*)(Y + off)     = r0;
        *(float4*)(Y + off + 4) = r1;
    }
}

// ---------------------------------------------------------------------------
extern "C" void kernel_launch(void* const* d_in, const int* in_sizes, int n_in,
                              void* d_out, int out_size) {
    const float* x      = (const float*)d_in[0];
    const float* w_attn = (const float*)d_in[1];
    const float* b_attn = (const float*)d_in[2];
    const float* w_proj = (const float*)d_in[3];
    const float* b_proj = (const float*)d_in[4];
    float* out = (float*)d_out;

    float *qkv, *q, *k, *v, *y, *ct, *st;
    __nv_bfloat16 *Abuf, *Bt1, *Bt2;
    cudaGetSymbolAddress((void**)&qkv,  g_qkv);
    cudaGetSymbolAddress((void**)&q,    g_q);
    cudaGetSymbolAddress((void**)&k,    g_k);
    cudaGetSymbolAddress((void**)&v,    g_v);
    cudaGetSymbolAddress((void**)&y,    g_y);
    cudaGetSymbolAddress((void**)&ct,   g_cos);
    cudaGetSymbolAddress((void**)&st,   g_sin);
    cudaGetSymbolAddress((void**)&Abuf, g_Abuf);
    cudaGetSymbolAddress((void**)&Bt1,  g_Bt1);
    cudaGetSymbolAddress((void**)&Bt2,  g_Bt2);

    cudaFuncSetAttribute(mma_gemm_kernel,
                         cudaFuncAttributeMaxDynamicSharedMemorySize, GEMM_SMEM);

    // RoPE tables
    build_rope_kernel<<<(SEQ * 64 + 255) / 256, 256>>>(ct, st);

    // Split-bf16 conversions for QKV GEMM
    convert_A_kernel<<<(MROWS * CDIM / 4 + 255) / 256, 256>>>(x, Abuf);
    convert_Bt_kernel<<<dim3(CDIM / 32, C3 / 32), dim3(32, 8)>>>(w_attn, Bt1, C3);

    // QKV projection (HMMA): [4096,6144] = A''[4096,6144] @ Bt1''^T + b_attn
    mma_gemm_kernel<<<dim3(C3 / 128, MROWS / 128), 256, GEMM_SMEM>>>(
        Abuf, Bt1, b_attn, qkv, C3);

    // RoPE + scatter into [B*H, T, D]
    rope_scatter_kernel<<<(BHTOT * SEQ * HDIM + 255) / 256, 256>>>(qkv, ct, st, q, k, v);

    // Flash attention -> y
    static const size_t fa_smem = (128*64 + 128*64 + 64*128 + 64*64) * sizeof(float);
    cudaFuncSetAttribute(flash_attn_kernel,
                         cudaFuncAttributeMaxDynamicSharedMemorySize, (int)fa_smem);
    flash_attn_kernel<<<dim3(SEQ / 64, BHTOT), 256, fa_smem>>>(q, k, v, y);

    // Split-bf16 conversions for output projection
    convert_A_kernel<<<(MROWS * CDIM / 4 + 255) / 256, 256>>>(y, Abuf);
    convert_Bt_kernel<<<dim3(CDIM / 32, CDIM / 32), dim3(32, 8)>>>(w_proj, Bt2, CDIM);

    // Output projection (HMMA) -> d_out
    mma_gemm_kernel<<<dim3(CDIM / 128, MROWS / 128), 256, GEMM_SMEM>>>(
        Abuf, Bt2, b_proj, out, CDIM);
}

// round 7
// speedup vs baseline: 3.1684x; 1.5961x over previous
#include <cuda_runtime.h>
#include <cuda_bf16.h>
#include <math.h>
#include <stdint.h>

// Problem constants
#define BATCH 4
#define SEQ   1024
#define CDIM  2048
#define NHEAD 16
#define HDIM  128
#define C3    (3*CDIM)
#define MROWS (BATCH*SEQ)      // 4096
#define BHTOT (BATCH*NHEAD)    // 64
#define KW    6144             // split K' = 3*2048 (both GEMMs)
#define NKITER 96              // KW / 64

// ---------------------------------------------------------------------------
// Scratch (__device__ globals; allocation-free rule)
// ---------------------------------------------------------------------------
__device__ float g_qkv[(size_t)MROWS * C3];
__device__ float g_y  [(size_t)MROWS * CDIM];
__device__ float g_cos[SEQ * 64];
__device__ float g_sin[SEQ * 64];
__device__ __nv_bfloat16 g_Abuf[(size_t)MROWS * KW];   // A'' [4096][6144]
__device__ __nv_bfloat16 g_Bt1 [(size_t)C3 * KW];      // w_attn^T'' [6144][6144]
__device__ __nv_bfloat16 g_Bt2 [(size_t)CDIM * KW];    // w_proj^T'' [2048][6144]
// Attention operands, split bf16:
__device__ __nv_bfloat16 g_qs[(size_t)BHTOT * SEQ * 256];  // [bh][t][hi128|lo128] (scaled)
__device__ __nv_bfloat16 g_ks[(size_t)BHTOT * SEQ * 256];  // [bh][t][hi128|lo128]
__device__ __nv_bfloat16 g_vt[(size_t)BHTOT * HDIM * 2 * SEQ]; // [bh][d][hi|lo][t]

// ---------------------------------------------------------------------------
// PTX helpers (arch-neutral: sm_80+ only — NO tcgen05, harness targets compute_103)
// ---------------------------------------------------------------------------
__device__ __forceinline__ uint32_t smem_u32(const void* p) {
    uint32_t a;
    asm("{ .reg .u64 t; cvta.to.shared.u64 t, %1; cvt.u32.u64 %0, t; }" : "=r"(a) : "l"(p));
    return a;
}
#define CP_ASYNC16(dst, src) \
    asm volatile("cp.async.cg.shared.global [%0], [%1], 16;" :: "r"(dst), "l"(src))
#define CP_COMMIT() asm volatile("cp.async.commit_group;" ::: "memory")
#define CP_WAIT(n)  asm volatile("cp.async.wait_group %0;" :: "n"(n) : "memory")

__device__ __forceinline__ void ldsm_x4(uint32_t& r0, uint32_t& r1, uint32_t& r2,
                                        uint32_t& r3, uint32_t addr) {
    asm volatile("ldmatrix.sync.aligned.m8n8.x4.shared.b16 {%0,%1,%2,%3}, [%4];"
                 : "=r"(r0), "=r"(r1), "=r"(r2), "=r"(r3) : "r"(addr));
}
__device__ __forceinline__ void mma_bf16(float& d0, float& d1, float& d2, float& d3,
                                         uint32_t a0, uint32_t a1, uint32_t a2, uint32_t a3,
                                         uint32_t b0, uint32_t b1) {
    asm volatile("mma.sync.aligned.m16n8k16.row.col.f32.bf16.bf16.f32 "
                 "{%0,%1,%2,%3}, {%4,%5,%6,%7}, {%8,%9}, {%0,%1,%2,%3};"
                 : "+f"(d0), "+f"(d1), "+f"(d2), "+f"(d3)
                 : "r"(a0), "r"(a1), "r"(a2), "r"(a3), "r"(b0), "r"(b1));
}
__device__ __forceinline__ uint32_t pack_bf16(float a, float b) {
    __nv_bfloat162 h = __floats2bfloat162_rn(a, b);
    return *(uint32_t*)&h;
}

// ---------------------------------------------------------------------------
// RoPE tables
// ---------------------------------------------------------------------------
__global__ void build_rope_kernel(float* __restrict__ ct, float* __restrict__ st) {
    int idx = blockIdx.x * blockDim.x + threadIdx.x;
    if (idx >= SEQ * 64) return;
    int t = idx >> 6;
    int i = idx & 63;
    double invf = pow(10000.0, -(double)i / 64.0);
    double ang  = (double)t * invf;
    ct[idx] = (float)cos(ang);
    st[idx] = (float)sin(ang);
}

// ---------------------------------------------------------------------------
// Split-bf16 conversion of activations: X fp32 [4096][2048] -> [4096][6144]
// ---------------------------------------------------------------------------
__global__ void convert_A_kernel(const float* __restrict__ X, __nv_bfloat16* __restrict__ out) {
    int idx = blockIdx.x * blockDim.x + threadIdx.x;
    if (idx >= MROWS * CDIM / 4) return;
    int m  = idx >> 9;
    int c4 = idx & 511;
    float4 v = ((const float4*)X)[idx];
    __nv_bfloat16 h0 = __float2bfloat16(v.x), h1 = __float2bfloat16(v.y);
    __nv_bfloat16 h2 = __float2bfloat16(v.z), h3 = __float2bfloat16(v.w);
    __nv_bfloat16 l0 = __float2bfloat16(v.x - __bfloat162float(h0));
    __nv_bfloat16 l1 = __float2bfloat16(v.y - __bfloat162float(h1));
    __nv_bfloat16 l2 = __float2bfloat16(v.z - __bfloat162float(h2));
    __nv_bfloat16 l3 = __float2bfloat16(v.w - __bfloat162float(h3));
    ushort4 hv = { __bfloat16_as_ushort(h0), __bfloat16_as_ushort(h1),
                   __bfloat16_as_ushort(h2), __bfloat16_as_ushort(h3) };
    ushort4 lv = { __bfloat16_as_ushort(l0), __bfloat16_as_ushort(l1),
                   __bfloat16_as_ushort(l2), __bfloat16_as_ushort(l3) };
    size_t ro = (size_t)m * KW + c4 * 4;
    *(ushort4*)((unsigned short*)out + ro)            = hv;
    *(ushort4*)((unsigned short*)out + ro + CDIM)     = hv;
    *(ushort4*)((unsigned short*)out + ro + 2 * CDIM) = lv;
}

// ---------------------------------------------------------------------------
// Split-bf16 + transpose of weights: W fp32 [2048][N] -> out bf16 [N][6144]
// ---------------------------------------------------------------------------
__global__ void convert_Bt_kernel(const float* __restrict__ W, __nv_bfloat16* __restrict__ out,
                                  int N) {
    __shared__ float t[32][33];
    int k0 = blockIdx.x * 32, n0 = blockIdx.y * 32;
    int tx = threadIdx.x, ty = threadIdx.y;   // (32, 8)
    #pragma unroll
    for (int r = 0; r < 32; r += 8)
        t[ty + r][tx] = W[(size_t)(k0 + ty + r) * N + n0 + tx];
    __syncthreads();
    #pragma unroll
    for (int r = 0; r < 32; r += 8) {
        int n = n0 + ty + r;
        int k = k0 + tx;
        float v = t[tx][ty + r];
        __nv_bfloat16 hi = __float2bfloat16(v);
        __nv_bfloat16 lo = __float2bfloat16(v - __bfloat162float(hi));
        size_t ro = (size_t)n * KW;
        out[ro + k]            = hi;
        out[ro + CDIM + k]     = lo;
        out[ro + 2 * CDIM + k] = hi;
    }
}

// ---------------------------------------------------------------------------
// mma.sync bf16 GEMM (unchanged from R3): C = A''@Bt''^T + bias
// ---------------------------------------------------------------------------
#define STAGES 3
#define STAGE_BYTES (32 * 1024)
#define GEMM_SMEM (STAGES * STAGE_BYTES + 1024)

__global__ __launch_bounds__(256, 2)
void mma_gemm_kernel(const __nv_bfloat16* __restrict__ A,
                     const __nv_bfloat16* __restrict__ Bt,
                     const float* __restrict__ bias,
                     float* __restrict__ C, int N) {
    extern __shared__ char smem_raw[];
    uint32_t smem_base = (smem_u32(smem_raw) + 1023u) & ~1023u;

    int tid  = threadIdx.x;
    int wid  = tid >> 5, lane = tid & 31;
    int wm   = wid >> 1;
    int wn   = wid & 1;

    int n0 = blockIdx.x * 128;
    int m0 = blockIdx.y * 128;

    const __nv_bfloat16* Ag0 = A  + (size_t)m0 * KW;
    const __nv_bfloat16* Bg0 = Bt + (size_t)n0 * KW;

    uint32_t a_off[2], a_xor[2];
    #pragma unroll
    for (int mi = 0; mi < 2; mi++) {
        int row = wm * 32 + mi * 16 + (lane & 15);
        a_off[mi] = (uint32_t)row * 128u;
        a_xor[mi] = (uint32_t)((row & 7) << 4);
    }
    uint32_t a_kb = (uint32_t)((lane >> 4) * 16);
    uint32_t b_off[4], b_xor[4];
    #pragma unroll
    for (int ng = 0; ng < 4; ng++) {
        int row = wn * 64 + ng * 16 + ((lane >> 4) << 3) + (lane & 7);
        b_off[ng] = 16384u + (uint32_t)row * 128u;
        b_xor[ng] = (uint32_t)((row & 7) << 4);
    }
    uint32_t b_kb = (uint32_t)(((lane >> 3) & 1) * 16);

    float d[2][8][4];
    #pragma unroll
    for (int mi = 0; mi < 2; mi++)
        #pragma unroll
        for (int ni = 0; ni < 8; ni++)
            #pragma unroll
            for (int c = 0; c < 4; c++) d[mi][ni][c] = 0.f;

    auto fill = [&](int s, int i) {
        int k0 = i * 64;
        uint32_t st_base = smem_base + s * STAGE_BYTES;
        const __nv_bfloat16* Ag = Ag0 + k0;
        #pragma unroll
        for (int j = 0; j < 4; j++) {
            int ch  = j * 256 + tid;
            int row = ch >> 3, col = ch & 7;
            uint32_t off = (uint32_t)row * 128u + (uint32_t)col * 16u;
            uint32_t dst = st_base + (off ^ ((off >> 3) & 0x70u));
            CP_ASYNC16(dst, Ag + (size_t)row * KW + col * 8);
        }
        const __nv_bfloat16* Bg = Bg0 + k0;
        #pragma unroll
        for (int j = 0; j < 4; j++) {
            int ch  = j * 256 + tid;
            int row = ch >> 3, col = ch & 7;
            uint32_t off = (uint32_t)row * 128u + (uint32_t)col * 16u;
            uint32_t dst = st_base + 16384u + (off ^ ((off >> 3) & 0x70u));
            CP_ASYNC16(dst, Bg + (size_t)row * KW + col * 8);
        }
    };

    fill(0, 0); CP_COMMIT();
    fill(1, 1); CP_COMMIT();

    for (int i = 0; i < NKITER; i++) {
        int s = i % STAGES;
        CP_WAIT(1);
        __syncthreads();

        uint32_t stb = smem_base + s * STAGE_BYTES;
        #pragma unroll
        for (int ks = 0; ks < 4; ks++) {
            uint32_t kk = (uint32_t)(ks * 32);
            uint32_t af[2][4];
            #pragma unroll
            for (int mi = 0; mi < 2; mi++) {
                uint32_t addr = stb + a_off[mi] + ((kk + a_kb) ^ a_xor[mi]);
                ldsm_x4(af[mi][0], af[mi][1], af[mi][2], af[mi][3], addr);
            }
            uint32_t bf[4][4];
            #pragma unroll
            for (int ng = 0; ng < 4; ng++) {
                uint32_t addr = stb + b_off[ng] + ((kk + b_kb) ^ b_xor[ng]);
                ldsm_x4(bf[ng][0], bf[ng][1], bf[ng][2], bf[ng][3], addr);
            }
            #pragma unroll
            for (int mi = 0; mi < 2; mi++)
                #pragma unroll
                for (int ni = 0; ni < 8; ni++) {
                    int ng = ni >> 1, sub = ni & 1;
                    mma_bf16(d[mi][ni][0], d[mi][ni][1], d[mi][ni][2], d[mi][ni][3],
                             af[mi][0], af[mi][1], af[mi][2], af[mi][3],
                             bf[ng][sub * 2], bf[ng][sub * 2 + 1]);
                }
        }
        __syncthreads();
        if (i + 2 < NKITER) fill((i + 2) % STAGES, i + 2);
        CP_COMMIT();
    }
    CP_WAIT(0);

    int row_base = m0 + wm * 32 + (lane >> 2);
    int col_base = n0 + wn * 64 + (lane & 3) * 2;
    #pragma unroll
    for (int ni = 0; ni < 8; ni++) {
        int col = col_base + ni * 8;
        float2 bs = *(const float2*)(bias + col);
        #pragma unroll
        for (int mi = 0; mi < 2; mi++) {
            int r0 = row_base + mi * 16;
            float2 v0 = { d[mi][ni][0] + bs.x, d[mi][ni][1] + bs.y };
            float2 v1 = { d[mi][ni][2] + bs.x, d[mi][ni][3] + bs.y };
            *(float2*)(C + (size_t)r0 * N + col)       = v0;
            *(float2*)(C + (size_t)(r0 + 8) * N + col) = v1;
        }
    }
}

// ---------------------------------------------------------------------------
// RoPE + split into bf16 hi/lo: qkv -> g_qs (scaled), g_ks  [bh][t][hi128|lo128]
// ---------------------------------------------------------------------------
__global__ void rope_split_kernel(const float* __restrict__ qkv,
                                  const float* __restrict__ ct,
                                  const float* __restrict__ st,
                                  __nv_bfloat16* __restrict__ qs,
                                  __nv_bfloat16* __restrict__ ks) {
    int idx = blockIdx.x * blockDim.x + threadIdx.x;
    if (idx >= BHTOT * SEQ * HDIM) return;
    int d  = idx & 127;
    int t  = (idx >> 7) & 1023;
    int bh = idx >> 17;
    int b  = bh >> 4;
    int h  = bh & 15;
    const float scale = 0.08838834764831845f;  // 1/sqrt(128)

    size_t base = (size_t)(b * SEQ + t) * C3 + h * HDIM;
    int i = d & 63;
    float c = ct[t * 64 + i];
    float s = st[t * 64 + i];
    float q1 = qkv[base + i];
    float q2 = qkv[base + i + 64];
    float k1 = qkv[base + CDIM + i];
    float k2 = qkv[base + CDIM + i + 64];
    float qo, ko;
    if (d < 64) { qo = q1 * c - q2 * s; ko = k1 * c - k2 * s; }
    else        { qo = q1 * s + q2 * c; ko = k1 * s + k2 * c; }
    qo *= scale;

    __nv_bfloat16 qh = __float2bfloat16(qo);
    __nv_bfloat16 ql = __float2bfloat16(qo - __bfloat162float(qh));
    __nv_bfloat16 kh = __float2bfloat16(ko);
    __nv_bfloat16 kl = __float2bfloat16(ko - __bfloat162float(kh));
    size_t ro = ((size_t)bh * SEQ + t) * 256;
    qs[ro + d]       = qh;
    qs[ro + 128 + d] = ql;
    ks[ro + d]       = kh;
    ks[ro + 128 + d] = kl;
}

// ---------------------------------------------------------------------------
// V transpose + split: qkv v-part [b][t][h][d] -> g_vt [bh][d][hi|lo][t]
// ---------------------------------------------------------------------------
__global__ void vt_split_kernel(const float* __restrict__ qkv,
                                __nv_bfloat16* __restrict__ vt) {
    __shared__ float tile[32][33];
    int t0 = blockIdx.x * 32;
    int d0 = blockIdx.y * 32;
    int bh = blockIdx.z;
    int b = bh >> 4, h = bh & 15;
    int tx = threadIdx.x, ty = threadIdx.y;  // (32, 8)
    #pragma unroll
    for (int r = 0; r < 32; r += 8)
        tile[ty + r][tx] = qkv[(size_t)(b * SEQ + t0 + ty + r) * C3 + 2 * CDIM + h * HDIM + d0 + tx];
    __syncthreads();
    #pragma unroll
    for (int r = 0; r < 32; r += 8) {
        int d = d0 + ty + r;
        int t = t0 + tx;
        float v = tile[tx][ty + r];
        __nv_bfloat16 hi = __float2bfloat16(v);
        __nv_bfloat16 lo = __float2bfloat16(v - __bfloat162float(hi));
        size_t base = (((size_t)bh * HDIM + d) * 2) * SEQ + t;
        vt[base]       = hi;
        vt[base + SEQ] = lo;
    }
}

// ---------------------------------------------------------------------------
// Tensor-core flash attention, split-bf16, causal.
// CTA: 64 q rows (one bh), 4 warps x 16 rows x full 32-col k-tile.
// smem: Q 64x[hi128|lo128] 32KB; 2 stages of (K 32x256 16KB + Vt 128x[hi32|lo32] 8KB... 16KB)
// ---------------------------------------------------------------------------
#define FA_SMEM (32768 + 2 * 32768 + 128)

__global__ __launch_bounds__(128, 2)
void flash_mma_kernel(const __nv_bfloat16* __restrict__ qs,
                      const __nv_bfloat16* __restrict__ ks,
                      const __nv_bfloat16* __restrict__ vt,
                      float* __restrict__ Y) {
    extern __shared__ char smraw[];
    uint32_t smQ = (smem_u32(smraw) + 127u) & ~127u;

    int tid  = threadIdx.x;
    int wid  = tid >> 5, lane = tid & 31;
    int qt   = blockIdx.x;
    int bh   = blockIdx.y;
    int q0   = qt * 64;
    int b = bh >> 4, h = bh & 15;

    // ---- Q tile fill (64 rows x 512B), one group with first KV ----
    const __nv_bfloat16* Qg = qs + ((size_t)bh * SEQ + q0) * 256;
    #pragma unroll
    for (int j = 0; j < 16; j++) {
        int ch = j * 128 + tid;          // 0..2047
        int row = ch >> 5, c16 = ch & 31;
        uint32_t dst = smQ + (uint32_t)row * 512u + (uint32_t)((c16 ^ (row & 7)) << 4);
        CP_ASYNC16(dst, Qg + (size_t)row * 256 + c16 * 8);
    }

    auto fillKV = [&](int s, int kt) {
        int k0 = kt * 32;
        uint32_t smK = smQ + 32768u + (uint32_t)s * 32768u;
        uint32_t smV = smK + 16384u;
        const __nv_bfloat16* Kg = ks + ((size_t)bh * SEQ + k0) * 256;
        #pragma unroll
        for (int j = 0; j < 8; j++) {
            int ch = j * 128 + tid;      // 0..1023
            int row = ch >> 5, c16 = ch & 31;
            uint32_t dst = smK + (uint32_t)row * 512u + (uint32_t)((c16 ^ (row & 7)) << 4);
            CP_ASYNC16(dst, Kg + (size_t)row * 256 + c16 * 8);
        }
        const __nv_bfloat16* Vg = vt + (size_t)bh * HDIM * 2 * SEQ + k0;
        #pragma unroll
        for (int j = 0; j < 8; j++) {
            int ch = j * 128 + tid;      // 0..1023
            int row = ch >> 3, c16 = ch & 7;     // row = d, c16: 0-3 hi, 4-7 lo
            int plane = c16 >> 2, tc = c16 & 3;
            uint32_t dst = smV + (uint32_t)row * 128u + (uint32_t)((c16 ^ (row & 7)) << 4);
            CP_ASYNC16(dst, Vg + ((size_t)row * 2 + plane) * SEQ + tc * 8);
        }
    };

    fillKV(0, 0);
    CP_COMMIT();

    float O[16][4];
    #pragma unroll
    for (int nf = 0; nf < 16; nf++)
        #pragma unroll
        for (int c = 0; c < 4; c++) O[nf][c] = 0.f;
    float mrow[2] = { -1e30f, -1e30f };
    float lrow[2] = { 0.f, 0.f };

    // ldmatrix per-thread coords
    int arow = wid * 16 + (lane & 15);
    uint32_t a_base = (uint32_t)arow * 512u;
    uint32_t a_x7   = (uint32_t)(arow & 7) << 4;
    uint32_t a_kb   = (uint32_t)((lane >> 4) << 4);
    int b_sub = ((lane >> 4) << 3) + (lane & 7);
    uint32_t b_kb = (uint32_t)(((lane >> 3) & 1) << 4);

    int nkt = 2 * qt + 2;
    for (int kt = 0; kt < nkt; kt++) {
        if (kt + 1 < nkt) { fillKV((kt + 1) & 1, kt + 1); CP_COMMIT(); CP_WAIT(1); }
        else              { CP_WAIT(0); }
        __syncthreads();

        uint32_t smK = smQ + 32768u + (uint32_t)(kt & 1) * 32768u;
        uint32_t smV = smK + 16384u;

        // ---- S = Qhi*Khi + Qhi*Klo + Qlo*Khi over D=128 ----
        float S[4][4];
        #pragma unroll
        for (int ni = 0; ni < 4; ni++)
            #pragma unroll
            for (int c = 0; c < 4; c++) S[ni][c] = 0.f;

        #pragma unroll
        for (int p = 0; p < 3; p++) {
            uint32_t qoff = (p == 2) ? 256u : 0u;
            uint32_t koff = (p == 1) ? 256u : 0u;
            #pragma unroll
            for (int kd = 0; kd < 8; kd++) {
                uint32_t a[4];
                ldsm_x4(a[0], a[1], a[2], a[3],
                        smQ + a_base + ((qoff + kd * 32 + a_kb) ^ a_x7));
                #pragma unroll
                for (int g = 0; g < 2; g++) {
                    int brow = g * 16 + b_sub;
                    uint32_t bf[4];
                    ldsm_x4(bf[0], bf[1], bf[2], bf[3],
                            smK + (uint32_t)brow * 512u +
                            ((koff + kd * 32 + b_kb) ^ ((uint32_t)(brow & 7) << 4)));
                    #pragma unroll
                    for (int sub = 0; sub < 2; sub++)
                        mma_bf16(S[g*2+sub][0], S[g*2+sub][1], S[g*2+sub][2], S[g*2+sub][3],
                                 a[0], a[1], a[2], a[3], bf[sub*2], bf[sub*2+1]);
                }
            }
        }

        // ---- causal mask (tiles overlapping the diagonal) ----
        if (kt >= 2 * qt) {
            int k0 = kt * 32;
            #pragma unroll
            for (int ni = 0; ni < 4; ni++) {
                #pragma unroll
                for (int c = 0; c < 4; c++) {
                    int gr = q0 + wid * 16 + (lane >> 2) + ((c >> 1) << 3);
                    int gc = k0 + ni * 8 + (lane & 3) * 2 + (c & 1);
                    if (gc > gr) S[ni][c] = -1e30f;
                }
            }
        }

        // ---- online softmax (rows owned exclusively per warp; quad shfl) ----
        uint32_t phi[2][4], plo[2][4];
        #pragma unroll
        for (int i = 0; i < 2; i++) {
            float vmax = -1e30f;
            #pragma unroll
            for (int ni = 0; ni < 4; ni++)
                vmax = fmaxf(vmax, fmaxf(S[ni][2*i], S[ni][2*i+1]));
            vmax = fmaxf(vmax, __shfl_xor_sync(0xffffffffu, vmax, 1));
            vmax = fmaxf(vmax, __shfl_xor_sync(0xffffffffu, vmax, 2));
            float mnew  = fmaxf(mrow[i], vmax);
            float alpha = __expf(mrow[i] - mnew);
            mrow[i] = mnew;
            float rs = 0.f;
            #pragma unroll
            for (int ni = 0; ni < 4; ni++) {
                float p0 = __expf(S[ni][2*i]   - mnew);
                float p1 = __expf(S[ni][2*i+1] - mnew);
                S[ni][2*i] = p0; S[ni][2*i+1] = p1;
                rs += p0 + p1;
            }
            rs += __shfl_xor_sync(0xffffffffu, rs, 1);
            rs += __shfl_xor_sync(0xffffffffu, rs, 2);
            lrow[i] = lrow[i] * alpha + rs;
            #pragma unroll
            for (int nf = 0; nf < 16; nf++) {
                O[nf][2*i]   *= alpha;
                O[nf][2*i+1] *= alpha;
            }
        }
        // P fragments in registers: A-frag layout == C-frag layout
        #pragma unroll
        for (int ks2 = 0; ks2 < 2; ks2++) {
            #pragma unroll
            for (int half = 0; half < 2; half++) {   // half0: k low8 (ni=2ks2), half1: high8
                int ni = 2 * ks2 + half;
                float p00 = S[ni][0], p01 = S[ni][1], p10 = S[ni][2], p11 = S[ni][3];
                __nv_bfloat16 h00 = __float2bfloat16(p00), h01 = __float2bfloat16(p01);
                __nv_bfloat16 h10 = __float2bfloat16(p10), h11 = __float2bfloat16(p11);
                phi[ks2][half*2+0] = pack_bf16(__bfloat162float(h00), __bfloat162float(h01));
                phi[ks2][half*2+1] = pack_bf16(__bfloat162float(h10), __bfloat162float(h11));
                plo[ks2][half*2+0] = pack_bf16(p00 - __bfloat162float(h00),
                                               p01 - __bfloat162float(h01));
                plo[ks2][half*2+1] = pack_bf16(p10 - __bfloat162float(h10),
                                               p11 - __bfloat162float(h11));
            }
        }
        // reorder: A frag = {r,klo},{r+8,klo},{r,khi},{r+8,khi} -> built as
        // [half*2+c] gives {r,klo},{r+8,klo},{r,khi},{r+8,khi} already. OK.

        // ---- O += Phi*Vhi + Phi*Vlo + Plo*Vhi ----
        #pragma unroll
        for (int p = 0; p < 3; p++) {
            uint32_t (*A)[4] = (p == 2) ? plo : phi;
            uint32_t voff = (p == 1) ? 64u : 0u;
            #pragma unroll
            for (int ks2 = 0; ks2 < 2; ks2++) {
                uint32_t koffb = voff + ks2 * 32;
                #pragma unroll
                for (int nb = 0; nb < 8; nb++) {
                    int brow = nb * 16 + b_sub;
                    uint32_t bv[4];
                    ldsm_x4(bv[0], bv[1], bv[2], bv[3],
                            smV + (uint32_t)brow * 128u +
                            ((koffb + b_kb) ^ ((uint32_t)(brow & 7) << 4)));
                    #pragma unroll
                    for (int sub = 0; sub < 2; sub++) {
                        int nf = nb * 2 + sub;
                        mma_bf16(O[nf][0], O[nf][1], O[nf][2], O[nf][3],
                                 A[ks2][0], A[ks2][1], A[ks2][2], A[ks2][3],
                                 bv[sub*2], bv[sub*2+1]);
                    }
                }
            }
        }
        __syncthreads();
    }

    // ---- epilogue: normalize + write y[b][t][h*128+d] ----
    #pragma unroll
    for (int i = 0; i < 2; i++) {
        float inv = 1.0f / lrow[i];
        int trow = q0 + wid * 16 + (lane >> 2) + 8 * i;
        float* yr = Y + (size_t)(b * SEQ + trow) * CDIM + h * HDIM + (lane & 3) * 2;
        #pragma unroll
        for (int nf = 0; nf < 16; nf++) {
            float2 v = { O[nf][2*i] * inv, O[nf][2*i+1] * inv };
            *(float2*)(yr + nf * 8) = v;
        }
    }
}

// ---------------------------------------------------------------------------
extern "C" void kernel_launch(void* const* d_in, const int* in_sizes, int n_in,
                              void* d_out, int out_size) {
    const float* x      = (const float*)d_in[0];
    const float* w_attn = (const float*)d_in[1];
    const float* b_attn = (const float*)d_in[2];
    const float* w_proj = (const float*)d_in[3];
    const float* b_proj = (const float*)d_in[4];
    float* out = (float*)d_out;

    float *qkv, *y, *ct, *st;
    __nv_bfloat16 *Abuf, *Bt1, *Bt2, *qsb, *ksb, *vtb;
    cudaGetSymbolAddress((void**)&qkv,  g_qkv);
    cudaGetSymbolAddress((void**)&y,    g_y);
    cudaGetSymbolAddress((void**)&ct,   g_cos);
    cudaGetSymbolAddress((void**)&st,   g_sin);
    cudaGetSymbolAddress((void**)&Abuf, g_Abuf);
    cudaGetSymbolAddress((void**)&Bt1,  g_Bt1);
    cudaGetSymbolAddress((void**)&Bt2,  g_Bt2);
    cudaGetSymbolAddress((void**)&qsb,  g_qs);
    cudaGetSymbolAddress((void**)&ksb,  g_ks);
    cudaGetSymbolAddress((void**)&vtb,  g_vt);

    cudaFuncSetAttribute(mma_gemm_kernel,
                         cudaFuncAttributeMaxDynamicSharedMemorySize, GEMM_SMEM);
    cudaFuncSetAttribute(flash_mma_kernel,
                         cudaFuncAttributeMaxDynamicSharedMemorySize, FA_SMEM);

    // RoPE tables
    build_rope_kernel<<<(SEQ * 64 + 255) / 256, 256>>>(ct, st);

    // Split-bf16 conversions for QKV GEMM
    convert_A_kernel<<<(MROWS * CDIM / 4 + 255) / 256, 256>>>(x, Abuf);
    convert_Bt_kernel<<<dim3(CDIM / 32, C3 / 32), dim3(32, 8)>>>(w_attn, Bt1, C3);

    // QKV projection (HMMA)
    mma_gemm_kernel<<<dim3(C3 / 128, MROWS / 128), 256, GEMM_SMEM>>>(
        Abuf, Bt1, b_attn, qkv, C3);

    // RoPE + split into bf16 hi/lo; V transpose + split
    rope_split_kernel<<<(BHTOT * SEQ * HDIM + 255) / 256, 256>>>(qkv, ct, st, qsb, ksb);
    vt_split_kernel<<<dim3(SEQ / 32, HDIM / 32, BHTOT), dim3(32, 8)>>>(qkv, vtb);

    // Tensor-core flash attention -> y
    flash_mma_kernel<<<dim3(SEQ / 64, BHTOT), 128, FA_SMEM>>>(qsb, ksb, vtb, y);

    // Split-bf16 conversions for output projection
    convert_A_kernel<<<(MROWS * CDIM / 4 + 255) / 256, 256>>>(y, Abuf);
    convert_Bt_kernel<<<dim3(CDIM / 32, CDIM / 32), dim3(32, 8)>>>(w_proj, Bt2, CDIM);

    // Output projection (HMMA) -> d_out
    mma_gemm_kernel<<<dim3(CDIM / 128, MROWS / 128), 256, GEMM_SMEM>>>(
        Abuf, Bt2, b_proj, out, CDIM);
}

// round 8
// speedup vs baseline: 3.2243x; 1.0176x over previous
#include <cuda_runtime.h>
#include <cuda_bf16.h>
#include <math.h>
#include <stdint.h>

// Problem constants
#define BATCH 4
#define SEQ   1024
#define CDIM  2048
#define NHEAD 16
#define HDIM  128
#define C3    (3*CDIM)
#define MROWS (BATCH*SEQ)      // 4096
#define BHTOT (BATCH*NHEAD)    // 64
#define KP    4096             // physical K width: [hi(2048) | lo(2048)]
#define NKITER 96              // logical K' = 6144 -> 96 chunks of 64

// ---------------------------------------------------------------------------
// Scratch (__device__ globals; allocation-free rule)
// ---------------------------------------------------------------------------
__device__ float g_qkv[(size_t)MROWS * C3];
__device__ float g_y  [(size_t)MROWS * CDIM];
__device__ float g_cos[SEQ * 64];
__device__ float g_sin[SEQ * 64];
__device__ __nv_bfloat16 g_Abuf[(size_t)MROWS * KP];   // A [hi|lo] [4096][4096]
__device__ __nv_bfloat16 g_Bt1 [(size_t)C3 * KP];      // w_attn^T [hi|lo] [6144][4096]
__device__ __nv_bfloat16 g_Bt2 [(size_t)CDIM * KP];    // w_proj^T [hi|lo] [2048][4096]
// Attention operands, split bf16:
__device__ __nv_bfloat16 g_qs[(size_t)BHTOT * SEQ * 256];  // [bh][t][hi128|lo128] (scaled)
__device__ __nv_bfloat16 g_ks[(size_t)BHTOT * SEQ * 256];  // [bh][t][hi128|lo128]
__device__ __nv_bfloat16 g_vt[(size_t)BHTOT * HDIM * 2 * SEQ]; // [bh][d][hi|lo][t]

// ---------------------------------------------------------------------------
// PTX helpers (arch-neutral: sm_80+ only — NO tcgen05, harness targets compute_103)
// ---------------------------------------------------------------------------
__device__ __forceinline__ uint32_t smem_u32(const void* p) {
    uint32_t a;
    asm("{ .reg .u64 t; cvta.to.shared.u64 t, %1; cvt.u32.u64 %0, t; }" : "=r"(a) : "l"(p));
    return a;
}
#define CP_ASYNC16(dst, src) \
    asm volatile("cp.async.cg.shared.global [%0], [%1], 16;" :: "r"(dst), "l"(src))
#define CP_COMMIT() asm volatile("cp.async.commit_group;" ::: "memory")
#define CP_WAIT(n)  asm volatile("cp.async.wait_group %0;" :: "n"(n) : "memory")

__device__ __forceinline__ void ldsm_x4(uint32_t& r0, uint32_t& r1, uint32_t& r2,
                                        uint32_t& r3, uint32_t addr) {
    asm volatile("ldmatrix.sync.aligned.m8n8.x4.shared.b16 {%0,%1,%2,%3}, [%4];"
                 : "=r"(r0), "=r"(r1), "=r"(r2), "=r"(r3) : "r"(addr));
}
__device__ __forceinline__ void mma_bf16(float& d0, float& d1, float& d2, float& d3,
                                         uint32_t a0, uint32_t a1, uint32_t a2, uint32_t a3,
                                         uint32_t b0, uint32_t b1) {
    asm volatile("mma.sync.aligned.m16n8k16.row.col.f32.bf16.bf16.f32 "
                 "{%0,%1,%2,%3}, {%4,%5,%6,%7}, {%8,%9}, {%0,%1,%2,%3};"
                 : "+f"(d0), "+f"(d1), "+f"(d2), "+f"(d3)
                 : "r"(a0), "r"(a1), "r"(a2), "r"(a3), "r"(b0), "r"(b1));
}
__device__ __forceinline__ uint32_t pack_bf16(float a, float b) {
    __nv_bfloat162 h = __floats2bfloat162_rn(a, b);
    return *(uint32_t*)&h;
}

// ---------------------------------------------------------------------------
// RoPE tables
// ---------------------------------------------------------------------------
__global__ void build_rope_kernel(float* __restrict__ ct, float* __restrict__ st) {
    int idx = blockIdx.x * blockDim.x + threadIdx.x;
    if (idx >= SEQ * 64) return;
    int t = idx >> 6;
    int i = idx & 63;
    double invf = pow(10000.0, -(double)i / 64.0);
    double ang  = (double)t * invf;
    ct[idx] = (float)cos(ang);
    st[idx] = (float)sin(ang);
}

// ---------------------------------------------------------------------------
// Split-bf16 conversion of activations: X fp32 [4096][2048] -> [4096][hi2048|lo2048]
// ---------------------------------------------------------------------------
__global__ void convert_A_kernel(const float* __restrict__ X, __nv_bfloat16* __restrict__ out) {
    int idx = blockIdx.x * blockDim.x + threadIdx.x;
    if (idx >= MROWS * CDIM / 4) return;
    int m  = idx >> 9;
    int c4 = idx & 511;
    float4 v = ((const float4*)X)[idx];
    __nv_bfloat16 h0 = __float2bfloat16(v.x), h1 = __float2bfloat16(v.y);
    __nv_bfloat16 h2 = __float2bfloat16(v.z), h3 = __float2bfloat16(v.w);
    __nv_bfloat16 l0 = __float2bfloat16(v.x - __bfloat162float(h0));
    __nv_bfloat16 l1 = __float2bfloat16(v.y - __bfloat162float(h1));
    __nv_bfloat16 l2 = __float2bfloat16(v.z - __bfloat162float(h2));
    __nv_bfloat16 l3 = __float2bfloat16(v.w - __bfloat162float(h3));
    ushort4 hv = { __bfloat16_as_ushort(h0), __bfloat16_as_ushort(h1),
                   __bfloat16_as_ushort(h2), __bfloat16_as_ushort(h3) };
    ushort4 lv = { __bfloat16_as_ushort(l0), __bfloat16_as_ushort(l1),
                   __bfloat16_as_ushort(l2), __bfloat16_as_ushort(l3) };
    size_t ro = (size_t)m * KP + c4 * 4;
    *(ushort4*)((unsigned short*)out + ro)        = hv;
    *(ushort4*)((unsigned short*)out + ro + CDIM) = lv;
}

// ---------------------------------------------------------------------------
// Split-bf16 + transpose of weights: W fp32 [2048][N] -> out bf16 [N][hi2048|lo2048]
// ---------------------------------------------------------------------------
__global__ void convert_Bt_kernel(const float* __restrict__ W, __nv_bfloat16* __restrict__ out,
                                  int N) {
    __shared__ float t[32][33];
    int k0 = blockIdx.x * 32, n0 = blockIdx.y * 32;
    int tx = threadIdx.x, ty = threadIdx.y;   // (32, 8)
    #pragma unroll
    for (int r = 0; r < 32; r += 8)
        t[ty + r][tx] = W[(size_t)(k0 + ty + r) * N + n0 + tx];
    __syncthreads();
    #pragma unroll
    for (int r = 0; r < 32; r += 8) {
        int n = n0 + ty + r;
        int k = k0 + tx;
        float v = t[tx][ty + r];
        __nv_bfloat16 hi = __float2bfloat16(v);
        __nv_bfloat16 lo = __float2bfloat16(v - __bfloat162float(hi));
        size_t ro = (size_t)n * KP;
        out[ro + k]        = hi;
        out[ro + CDIM + k] = lo;
    }
}

// ---------------------------------------------------------------------------
// mma.sync bf16 GEMM: C = A''@Bt''^T + bias, with logical K' = 6144 mapped onto
// physical [hi|lo] planes: logical chunk i (64 K each) reads
//   A: chunks [hi 0..31 | hi 0..31 | lo 32..63]  -> physA(i) = i<32 ? i : i-32
//   B: chunks [hi 0..31 | lo 32..63 | hi 0..31]  -> physB(i) = i<64 ? i : i-64
// CTA tile 128x128, BK=64, 3-stage cp.async ring, single __syncthreads/iter,
// fill-before-compute.
// ---------------------------------------------------------------------------
#define STAGES 3
#define STAGE_BYTES (32 * 1024)
#define GEMM_SMEM (STAGES * STAGE_BYTES + 1024)

__global__ __launch_bounds__(256, 2)
void mma_gemm_kernel(const __nv_bfloat16* __restrict__ A,
                     const __nv_bfloat16* __restrict__ Bt,
                     const float* __restrict__ bias,
                     float* __restrict__ C, int N) {
    extern __shared__ char smem_raw[];
    uint32_t smem_base = (smem_u32(smem_raw) + 1023u) & ~1023u;

    int tid  = threadIdx.x;
    int wid  = tid >> 5, lane = tid & 31;
    int wm   = wid >> 1;
    int wn   = wid & 1;

    int n0 = blockIdx.x * 128;
    int m0 = blockIdx.y * 128;

    const __nv_bfloat16* Ag0 = A  + (size_t)m0 * KP;
    const __nv_bfloat16* Bg0 = Bt + (size_t)n0 * KP;

    uint32_t a_off[2], a_xor[2];
    #pragma unroll
    for (int mi = 0; mi < 2; mi++) {
        int row = wm * 32 + mi * 16 + (lane & 15);
        a_off[mi] = (uint32_t)row * 128u;
        a_xor[mi] = (uint32_t)((row & 7) << 4);
    }
    uint32_t a_kb = (uint32_t)((lane >> 4) * 16);
    uint32_t b_off[4], b_xor[4];
    #pragma unroll
    for (int ng = 0; ng < 4; ng++) {
        int row = wn * 64 + ng * 16 + ((lane >> 4) << 3) + (lane & 7);
        b_off[ng] = 16384u + (uint32_t)row * 128u;
        b_xor[ng] = (uint32_t)((row & 7) << 4);
    }
    uint32_t b_kb = (uint32_t)(((lane >> 3) & 1) * 16);

    float d[2][8][4];
    #pragma unroll
    for (int mi = 0; mi < 2; mi++)
        #pragma unroll
        for (int ni = 0; ni < 8; ni++)
            #pragma unroll
            for (int c = 0; c < 4; c++) d[mi][ni][c] = 0.f;

    // per-thread fill coords (precomputed)
    int f_row = tid >> 1;            // 0..127 (2 chunks of 16B per row per quarter)
    int f_col = tid & 1;             // base 16B col
    auto fill = [&](int s, int i) {
        int ia = (i < 32) ? i : i - 32;   // A physical chunk
        int ib = (i < 64) ? i : i - 64;   // B physical chunk
        uint32_t st_base = smem_base + s * STAGE_BYTES;
        const __nv_bfloat16* Ag = Ag0 + ia * 64;
        #pragma unroll
        for (int j = 0; j < 4; j++) {
            int ch  = j * 256 + tid;
            int row = ch >> 3, col = ch & 7;
            uint32_t off = (uint32_t)row * 128u + (uint32_t)col * 16u;
            uint32_t dst = st_base + (off ^ ((off >> 3) & 0x70u));
            CP_ASYNC16(dst, Ag + (size_t)row * KP + col * 8);
        }
        const __nv_bfloat16* Bg = Bg0 + ib * 64;
        #pragma unroll
        for (int j = 0; j < 4; j++) {
            int ch  = j * 256 + tid;
            int row = ch >> 3, col = ch & 7;
            uint32_t off = (uint32_t)row * 128u + (uint32_t)col * 16u;
            uint32_t dst = st_base + 16384u + (off ^ ((off >> 3) & 0x70u));
            CP_ASYNC16(dst, Bg + (size_t)row * KP + col * 8);
        }
    };
    (void)f_row; (void)f_col;

    fill(0, 0); CP_COMMIT();
    fill(1, 1); CP_COMMIT();

    for (int i = 0; i < NKITER; i++) {
        int s = i % STAGES;
        CP_WAIT(1);
        __syncthreads();
        // fill next-next stage BEFORE compute (its last reader finished at i-1,
        // which the barrier above just ordered)
        if (i + 2 < NKITER) fill((i + 2) % STAGES, i + 2);
        CP_COMMIT();

        uint32_t stb = smem_base + s * STAGE_BYTES;
        #pragma unroll
        for (int ks = 0; ks < 4; ks++) {
            uint32_t kk = (uint32_t)(ks * 32);
            uint32_t af[2][4];
            #pragma unroll
            for (int mi = 0; mi < 2; mi++) {
                uint32_t addr = stb + a_off[mi] + ((kk + a_kb) ^ a_xor[mi]);
                ldsm_x4(af[mi][0], af[mi][1], af[mi][2], af[mi][3], addr);
            }
            uint32_t bf[4][4];
            #pragma unroll
            for (int ng = 0; ng < 4; ng++) {
                uint32_t addr = stb + b_off[ng] + ((kk + b_kb) ^ b_xor[ng]);
                ldsm_x4(bf[ng][0], bf[ng][1], bf[ng][2], bf[ng][3], addr);
            }
            #pragma unroll
            for (int mi = 0; mi < 2; mi++)
                #pragma unroll
                for (int ni = 0; ni < 8; ni++) {
                    int ng = ni >> 1, sub = ni & 1;
                    mma_bf16(d[mi][ni][0], d[mi][ni][1], d[mi][ni][2], d[mi][ni][3],
                             af[mi][0], af[mi][1], af[mi][2], af[mi][3],
                             bf[ng][sub * 2], bf[ng][sub * 2 + 1]);
                }
        }
    }
    CP_WAIT(0);

    int row_base = m0 + wm * 32 + (lane >> 2);
    int col_base = n0 + wn * 64 + (lane & 3) * 2;
    #pragma unroll
    for (int ni = 0; ni < 8; ni++) {
        int col = col_base + ni * 8;
        float2 bs = *(const float2*)(bias + col);
        #pragma unroll
        for (int mi = 0; mi < 2; mi++) {
            int r0 = row_base + mi * 16;
            float2 v0 = { d[mi][ni][0] + bs.x, d[mi][ni][1] + bs.y };
            float2 v1 = { d[mi][ni][2] + bs.x, d[mi][ni][3] + bs.y };
            *(float2*)(C + (size_t)r0 * N + col)       = v0;
            *(float2*)(C + (size_t)(r0 + 8) * N + col) = v1;
        }
    }
}

// ---------------------------------------------------------------------------
// RoPE + split into bf16 hi/lo: qkv -> g_qs (scaled), g_ks  [bh][t][hi128|lo128]
// ---------------------------------------------------------------------------
__global__ void rope_split_kernel(const float* __restrict__ qkv,
                                  const float* __restrict__ ct,
                                  const float* __restrict__ st,
                                  __nv_bfloat16* __restrict__ qs,
                                  __nv_bfloat16* __restrict__ ks) {
    int idx = blockIdx.x * blockDim.x + threadIdx.x;
    if (idx >= BHTOT * SEQ * HDIM) return;
    int d  = idx & 127;
    int t  = (idx >> 7) & 1023;
    int bh = idx >> 17;
    int b  = bh >> 4;
    int h  = bh & 15;
    const float scale = 0.08838834764831845f;  // 1/sqrt(128)

    size_t base = (size_t)(b * SEQ + t) * C3 + h * HDIM;
    int i = d & 63;
    float c = ct[t * 64 + i];
    float s = st[t * 64 + i];
    float q1 = qkv[base + i];
    float q2 = qkv[base + i + 64];
    float k1 = qkv[base + CDIM + i];
    float k2 = qkv[base + CDIM + i + 64];
    float qo, ko;
    if (d < 64) { qo = q1 * c - q2 * s; ko = k1 * c - k2 * s; }
    else        { qo = q1 * s + q2 * c; ko = k1 * s + k2 * c; }
    qo *= scale;

    __nv_bfloat16 qh = __float2bfloat16(qo);
    __nv_bfloat16 ql = __float2bfloat16(qo - __bfloat162float(qh));
    __nv_bfloat16 kh = __float2bfloat16(ko);
    __nv_bfloat16 kl = __float2bfloat16(ko - __bfloat162float(kh));
    size_t ro = ((size_t)bh * SEQ + t) * 256;
    qs[ro + d]       = qh;
    qs[ro + 128 + d] = ql;
    ks[ro + d]       = kh;
    ks[ro + 128 + d] = kl;
}

// ---------------------------------------------------------------------------
// V transpose + split: qkv v-part [b][t][h][d] -> g_vt [bh][d][hi|lo][t]
// ---------------------------------------------------------------------------
__global__ void vt_split_kernel(const float* __restrict__ qkv,
                                __nv_bfloat16* __restrict__ vt) {
    __shared__ float tile[32][33];
    int t0 = blockIdx.x * 32;
    int d0 = blockIdx.y * 32;
    int bh = blockIdx.z;
    int b = bh >> 4, h = bh & 15;
    int tx = threadIdx.x, ty = threadIdx.y;  // (32, 8)
    #pragma unroll
    for (int r = 0; r < 32; r += 8)
        tile[ty + r][tx] = qkv[(size_t)(b * SEQ + t0 + ty + r) * C3 + 2 * CDIM + h * HDIM + d0 + tx];
    __syncthreads();
    #pragma unroll
    for (int r = 0; r < 32; r += 8) {
        int d = d0 + ty + r;
        int t = t0 + tx;
        float v = tile[tx][ty + r];
        __nv_bfloat16 hi = __float2bfloat16(v);
        __nv_bfloat16 lo = __float2bfloat16(v - __bfloat162float(hi));
        size_t base = (((size_t)bh * HDIM + d) * 2) * SEQ + t;
        vt[base]       = hi;
        vt[base + SEQ] = lo;
    }
}

// ---------------------------------------------------------------------------
// Tensor-core flash attention, split-bf16, causal.
// CTA: 64 q rows (one bh), 4 warps x 16 rows x full 32-col k-tile.
// ---------------------------------------------------------------------------
#define FA_SMEM (32768 + 2 * 32768 + 128)

__global__ __launch_bounds__(128, 2)
void flash_mma_kernel(const __nv_bfloat16* __restrict__ qs,
                      const __nv_bfloat16* __restrict__ ks,
                      const __nv_bfloat16* __restrict__ vt,
                      float* __restrict__ Y) {
    extern __shared__ char smraw[];
    uint32_t smQ = (smem_u32(smraw) + 127u) & ~127u;

    int tid  = threadIdx.x;
    int wid  = tid >> 5, lane = tid & 31;
    int qt   = blockIdx.x;
    int bh   = blockIdx.y;
    int q0   = qt * 64;
    int b = bh >> 4, h = bh & 15;

    const __nv_bfloat16* Qg = qs + ((size_t)bh * SEQ + q0) * 256;
    #pragma unroll
    for (int j = 0; j < 16; j++) {
        int ch = j * 128 + tid;
        int row = ch >> 5, c16 = ch & 31;
        uint32_t dst = smQ + (uint32_t)row * 512u + (uint32_t)((c16 ^ (row & 7)) << 4);
        CP_ASYNC16(dst, Qg + (size_t)row * 256 + c16 * 8);
    }

    auto fillKV = [&](int s, int kt) {
        int k0 = kt * 32;
        uint32_t smK = smQ + 32768u + (uint32_t)s * 32768u;
        uint32_t smV = smK + 16384u;
        const __nv_bfloat16* Kg = ks + ((size_t)bh * SEQ + k0) * 256;
        #pragma unroll
        for (int j = 0; j < 8; j++) {
            int ch = j * 128 + tid;
            int row = ch >> 5, c16 = ch & 31;
            uint32_t dst = smK + (uint32_t)row * 512u + (uint32_t)((c16 ^ (row & 7)) << 4);
            CP_ASYNC16(dst, Kg + (size_t)row * 256 + c16 * 8);
        }
        const __nv_bfloat16* Vg = vt + (size_t)bh * HDIM * 2 * SEQ + k0;
        #pragma unroll
        for (int j = 0; j < 8; j++) {
            int ch = j * 128 + tid;
            int row = ch >> 3, c16 = ch & 7;
            int plane = c16 >> 2, tc = c16 & 3;
            uint32_t dst = smV + (uint32_t)row * 128u + (uint32_t)((c16 ^ (row & 7)) << 4);
            CP_ASYNC16(dst, Vg + ((size_t)row * 2 + plane) * SEQ + tc * 8);
        }
    };

    fillKV(0, 0);
    CP_COMMIT();

    float O[16][4];
    #pragma unroll
    for (int nf = 0; nf < 16; nf++)
        #pragma unroll
        for (int c = 0; c < 4; c++) O[nf][c] = 0.f;
    float mrow[2] = { -1e30f, -1e30f };
    float lrow[2] = { 0.f, 0.f };

    int arow = wid * 16 + (lane & 15);
    uint32_t a_base = (uint32_t)arow * 512u;
    uint32_t a_x7   = (uint32_t)(arow & 7) << 4;
    uint32_t a_kb   = (uint32_t)((lane >> 4) << 4);
    int b_sub = ((lane >> 4) << 3) + (lane & 7);
    uint32_t b_kb = (uint32_t)(((lane >> 3) & 1) << 4);

    int nkt = 2 * qt + 2;
    for (int kt = 0; kt < nkt; kt++) {
        if (kt + 1 < nkt) { fillKV((kt + 1) & 1, kt + 1); CP_COMMIT(); CP_WAIT(1); }
        else              { CP_WAIT(0); }
        __syncthreads();

        uint32_t smK = smQ + 32768u + (uint32_t)(kt & 1) * 32768u;
        uint32_t smV = smK + 16384u;

        float S[4][4];
        #pragma unroll
        for (int ni = 0; ni < 4; ni++)
            #pragma unroll
            for (int c = 0; c < 4; c++) S[ni][c] = 0.f;

        #pragma unroll
        for (int p = 0; p < 3; p++) {
            uint32_t qoff = (p == 2) ? 256u : 0u;
            uint32_t koff = (p == 1) ? 256u : 0u;
            #pragma unroll
            for (int kd = 0; kd < 8; kd++) {
                uint32_t a[4];
                ldsm_x4(a[0], a[1], a[2], a[3],
                        smQ + a_base + ((qoff + kd * 32 + a_kb) ^ a_x7));
                #pragma unroll
                for (int g = 0; g < 2; g++) {
                    int brow = g * 16 + b_sub;
                    uint32_t bf[4];
                    ldsm_x4(bf[0], bf[1], bf[2], bf[3],
                            smK + (uint32_t)brow * 512u +
                            ((koff + kd * 32 + b_kb) ^ ((uint32_t)(brow & 7) << 4)));
                    #pragma unroll
                    for (int sub = 0; sub < 2; sub++)
                        mma_bf16(S[g*2+sub][0], S[g*2+sub][1], S[g*2+sub][2], S[g*2+sub][3],
                                 a[0], a[1], a[2], a[3], bf[sub*2], bf[sub*2+1]);
                }
            }
        }

        if (kt >= 2 * qt) {
            int k0 = kt * 32;
            #pragma unroll
            for (int ni = 0; ni < 4; ni++) {
                #pragma unroll
                for (int c = 0; c < 4; c++) {
                    int gr = q0 + wid * 16 + (lane >> 2) + ((c >> 1) << 3);
                    int gc = k0 + ni * 8 + (lane & 3) * 2 + (c & 1);
                    if (gc > gr) S[ni][c] = -1e30f;
                }
            }
        }

        uint32_t phi[2][4], plo[2][4];
        #pragma unroll
        for (int i = 0; i < 2; i++) {
            float vmax = -1e30f;
            #pragma unroll
            for (int ni = 0; ni < 4; ni++)
                vmax = fmaxf(vmax, fmaxf(S[ni][2*i], S[ni][2*i+1]));
            vmax = fmaxf(vmax, __shfl_xor_sync(0xffffffffu, vmax, 1));
            vmax = fmaxf(vmax, __shfl_xor_sync(0xffffffffu, vmax, 2));
            float mnew  = fmaxf(mrow[i], vmax);
            float alpha = __expf(mrow[i] - mnew);
            mrow[i] = mnew;
            float rs = 0.f;
            #pragma unroll
            for (int ni = 0; ni < 4; ni++) {
                float p0 = __expf(S[ni][2*i]   - mnew);
                float p1 = __expf(S[ni][2*i+1] - mnew);
                S[ni][2*i] = p0; S[ni][2*i+1] = p1;
                rs += p0 + p1;
            }
            rs += __shfl_xor_sync(0xffffffffu, rs, 1);
            rs += __shfl_xor_sync(0xffffffffu, rs, 2);
            lrow[i] = lrow[i] * alpha + rs;
            #pragma unroll
            for (int nf = 0; nf < 16; nf++) {
                O[nf][2*i]   *= alpha;
                O[nf][2*i+1] *= alpha;
            }
        }
        #pragma unroll
        for (int ks2 = 0; ks2 < 2; ks2++) {
            #pragma unroll
            for (int half = 0; half < 2; half++) {
                int ni = 2 * ks2 + half;
                float p00 = S[ni][0], p01 = S[ni][1], p10 = S[ni][2], p11 = S[ni][3];
                __nv_bfloat16 h00 = __float2bfloat16(p00), h01 = __float2bfloat16(p01);
                __nv_bfloat16 h10 = __float2bfloat16(p10), h11 = __float2bfloat16(p11);
                phi[ks2][half*2+0] = pack_bf16(__bfloat162float(h00), __bfloat162float(h01));
                phi[ks2][half*2+1] = pack_bf16(__bfloat162float(h10), __bfloat162float(h11));
                plo[ks2][half*2+0] = pack_bf16(p00 - __bfloat162float(h00),
                                               p01 - __bfloat162float(h01));
                plo[ks2][half*2+1] = pack_bf16(p10 - __bfloat162float(h10),
                                               p11 - __bfloat162float(h11));
            }
        }

        #pragma unroll
        for (int p = 0; p < 3; p++) {
            uint32_t (*A)[4] = (p == 2) ? plo : phi;
            uint32_t voff = (p == 1) ? 64u : 0u;
            #pragma unroll
            for (int ks2 = 0; ks2 < 2; ks2++) {
                uint32_t koffb = voff + ks2 * 32;
                #pragma unroll
                for (int nb = 0; nb < 8; nb++) {
                    int brow = nb * 16 + b_sub;
                    uint32_t bv[4];
                    ldsm_x4(bv[0], bv[1], bv[2], bv[3],
                            smV + (uint32_t)brow * 128u +
                            ((koffb + b_kb) ^ ((uint32_t)(brow & 7) << 4)));
                    #pragma unroll
                    for (int sub = 0; sub < 2; sub++) {
                        int nf = nb * 2 + sub;
                        mma_bf16(O[nf][0], O[nf][1], O[nf][2], O[nf][3],
                                 A[ks2][0], A[ks2][1], A[ks2][2], A[ks2][3],
                                 bv[sub*2], bv[sub*2+1]);
                    }
                }
            }
        }
        __syncthreads();
    }

    #pragma unroll
    for (int i = 0; i < 2; i++) {
        float inv = 1.0f / lrow[i];
        int trow = q0 + wid * 16 + (lane >> 2) + 8 * i;
        float* yr = Y + (size_t)(b * SEQ + trow) * CDIM + h * HDIM + (lane & 3) * 2;
        #pragma unroll
        for (int nf = 0; nf < 16; nf++) {
            float2 v = { O[nf][2*i] * inv, O[nf][2*i+1] * inv };
            *(float2*)(yr + nf * 8) = v;
        }
    }
}

// ---------------------------------------------------------------------------
extern "C" void kernel_launch(void* const* d_in, const int* in_sizes, int n_in,
                              void* d_out, int out_size) {
    const float* x      = (const float*)d_in[0];
    const float* w_attn = (const float*)d_in[1];
    const float* b_attn = (const float*)d_in[2];
    const float* w_proj = (const float*)d_in[3];
    const float* b_proj = (const float*)d_in[4];
    float* out = (float*)d_out;

    float *qkv, *y, *ct, *st;
    __nv_bfloat16 *Abuf, *Bt1, *Bt2, *qsb, *ksb, *vtb;
    cudaGetSymbolAddress((void**)&qkv,  g_qkv);
    cudaGetSymbolAddress((void**)&y,    g_y);
    cudaGetSymbolAddress((void**)&ct,   g_cos);
    cudaGetSymbolAddress((void**)&st,   g_sin);
    cudaGetSymbolAddress((void**)&Abuf, g_Abuf);
    cudaGetSymbolAddress((void**)&Bt1,  g_Bt1);
    cudaGetSymbolAddress((void**)&Bt2,  g_Bt2);
    cudaGetSymbolAddress((void**)&qsb,  g_qs);
    cudaGetSymbolAddress((void**)&ksb,  g_ks);
    cudaGetSymbolAddress((void**)&vtb,  g_vt);

    cudaFuncSetAttribute(mma_gemm_kernel,
                         cudaFuncAttributeMaxDynamicSharedMemorySize, GEMM_SMEM);
    cudaFuncSetAttribute(flash_mma_kernel,
                         cudaFuncAttributeMaxDynamicSharedMemorySize, FA_SMEM);

    // RoPE tables
    build_rope_kernel<<<(SEQ * 64 + 255) / 256, 256>>>(ct, st);

    // Split-bf16 conversions for QKV GEMM
    convert_A_kernel<<<(MROWS * CDIM / 4 + 255) / 256, 256>>>(x, Abuf);
    convert_Bt_kernel<<<dim3(CDIM / 32, C3 / 32), dim3(32, 8)>>>(w_attn, Bt1, C3);

    // QKV projection (HMMA)
    mma_gemm_kernel<<<dim3(C3 / 128, MROWS / 128), 256, GEMM_SMEM>>>(
        Abuf, Bt1, b_attn, qkv, C3);

    // RoPE + split into bf16 hi/lo; V transpose + split
    rope_split_kernel<<<(BHTOT * SEQ * HDIM + 255) / 256, 256>>>(qkv, ct, st, qsb, ksb);
    vt_split_kernel<<<dim3(SEQ / 32, HDIM / 32, BHTOT), dim3(32, 8)>>>(qkv, vtb);

    // Tensor-core flash attention -> y
    flash_mma_kernel<<<dim3(SEQ / 64, BHTOT), 128, FA_SMEM>>>(qsb, ksb, vtb, y);

    // Split-bf16 conversions for output projection
    convert_A_kernel<<<(MROWS * CDIM / 4 + 255) / 256, 256>>>(y, Abuf);
    convert_Bt_kernel<<<dim3(CDIM / 32, CDIM / 32), dim3(32, 8)>>>(w_proj, Bt2, CDIM);

    // Output projection (HMMA) -> d_out
    mma_gemm_kernel<<<dim3(CDIM / 128, MROWS / 128), 256, GEMM_SMEM>>>(
        Abuf, Bt2, b_proj, out, CDIM);
}

// round 9
// speedup vs baseline: 3.3765x; 1.0472x over previous
#include <cuda_runtime.h>
#include <cuda_bf16.h>
#include <math.h>
#include <stdint.h>

// Problem constants
#define BATCH 4
#define SEQ   1024
#define CDIM  2048
#define NHEAD 16
#define HDIM  128
#define C3    (3*CDIM)
#define MROWS (BATCH*SEQ)      // 4096
#define BHTOT (BATCH*NHEAD)    // 64
#define KP    4096             // physical K width: [hi(2048) | lo(2048)]
#define NKITER 96              // logical K' = 6144 -> 96 chunks of 64

// ---------------------------------------------------------------------------
// Scratch (__device__ globals; allocation-free rule)
// ---------------------------------------------------------------------------
__device__ float g_qkv[(size_t)MROWS * C3];
__device__ float g_y  [(size_t)MROWS * CDIM];
__device__ float g_cos[SEQ * 64];
__device__ float g_sin[SEQ * 64];
__device__ __nv_bfloat16 g_Abuf[(size_t)MROWS * KP];   // A [hi|lo] [4096][4096]
__device__ __nv_bfloat16 g_Bt1 [(size_t)C3 * KP];      // w_attn^T [hi|lo] [6144][4096]
__device__ __nv_bfloat16 g_Bt2 [(size_t)CDIM * KP];    // w_proj^T [hi|lo] [2048][4096]
// Attention operands, split bf16:
__device__ __nv_bfloat16 g_qs[(size_t)BHTOT * SEQ * 256];  // [bh][t][hi128|lo128] (scaled)
__device__ __nv_bfloat16 g_ks[(size_t)BHTOT * SEQ * 256];  // [bh][t][hi128|lo128]
__device__ __nv_bfloat16 g_vt[(size_t)BHTOT * HDIM * 2 * SEQ]; // [bh][d][hi|lo][t]

// ---------------------------------------------------------------------------
// PTX helpers (arch-neutral: sm_80+ only — NO tcgen05, harness targets compute_103)
// ---------------------------------------------------------------------------
__device__ __forceinline__ uint32_t smem_u32(const void* p) {
    uint32_t a;
    asm("{ .reg .u64 t; cvta.to.shared.u64 t, %1; cvt.u32.u64 %0, t; }" : "=r"(a) : "l"(p));
    return a;
}
#define CP_ASYNC16(dst, src) \
    asm volatile("cp.async.cg.shared.global [%0], [%1], 16;" :: "r"(dst), "l"(src))
#define CP_COMMIT() asm volatile("cp.async.commit_group;" ::: "memory")
#define CP_WAIT(n)  asm volatile("cp.async.wait_group %0;" :: "n"(n) : "memory")

__device__ __forceinline__ void ldsm_x4(uint32_t& r0, uint32_t& r1, uint32_t& r2,
                                        uint32_t& r3, uint32_t addr) {
    asm volatile("ldmatrix.sync.aligned.m8n8.x4.shared.b16 {%0,%1,%2,%3}, [%4];"
                 : "=r"(r0), "=r"(r1), "=r"(r2), "=r"(r3) : "r"(addr));
}
__device__ __forceinline__ void mma_bf16(float& d0, float& d1, float& d2, float& d3,
                                         uint32_t a0, uint32_t a1, uint32_t a2, uint32_t a3,
                                         uint32_t b0, uint32_t b1) {
    asm volatile("mma.sync.aligned.m16n8k16.row.col.f32.bf16.bf16.f32 "
                 "{%0,%1,%2,%3}, {%4,%5,%6,%7}, {%8,%9}, {%0,%1,%2,%3};"
                 : "+f"(d0), "+f"(d1), "+f"(d2), "+f"(d3)
                 : "r"(a0), "r"(a1), "r"(a2), "r"(a3), "r"(b0), "r"(b1));
}
__device__ __forceinline__ uint32_t pack_bf16(float a, float b) {
    __nv_bfloat162 h = __floats2bfloat162_rn(a, b);
    return *(uint32_t*)&h;
}

// ---------------------------------------------------------------------------
// RoPE tables
// ---------------------------------------------------------------------------
__global__ void build_rope_kernel(float* __restrict__ ct, float* __restrict__ st) {
    int idx = blockIdx.x * blockDim.x + threadIdx.x;
    if (idx >= SEQ * 64) return;
    int t = idx >> 6;
    int i = idx & 63;
    double invf = pow(10000.0, -(double)i / 64.0);
    double ang  = (double)t * invf;
    ct[idx] = (float)cos(ang);
    st[idx] = (float)sin(ang);
}

// ---------------------------------------------------------------------------
// Split-bf16 conversion of activations: X fp32 [4096][2048] -> [4096][hi2048|lo2048]
// ---------------------------------------------------------------------------
__global__ void convert_A_kernel(const float* __restrict__ X, __nv_bfloat16* __restrict__ out) {
    int idx = blockIdx.x * blockDim.x + threadIdx.x;
    if (idx >= MROWS * CDIM / 4) return;
    int m  = idx >> 9;
    int c4 = idx & 511;
    float4 v = ((const float4*)X)[idx];
    __nv_bfloat16 h0 = __float2bfloat16(v.x), h1 = __float2bfloat16(v.y);
    __nv_bfloat16 h2 = __float2bfloat16(v.z), h3 = __float2bfloat16(v.w);
    __nv_bfloat16 l0 = __float2bfloat16(v.x - __bfloat162float(h0));
    __nv_bfloat16 l1 = __float2bfloat16(v.y - __bfloat162float(h1));
    __nv_bfloat16 l2 = __float2bfloat16(v.z - __bfloat162float(h2));
    __nv_bfloat16 l3 = __float2bfloat16(v.w - __bfloat162float(h3));
    ushort4 hv = { __bfloat16_as_ushort(h0), __bfloat16_as_ushort(h1),
                   __bfloat16_as_ushort(h2), __bfloat16_as_ushort(h3) };
    ushort4 lv = { __bfloat16_as_ushort(l0), __bfloat16_as_ushort(l1),
                   __bfloat16_as_ushort(l2), __bfloat16_as_ushort(l3) };
    size_t ro = (size_t)m * KP + c4 * 4;
    *(ushort4*)((unsigned short*)out + ro)        = hv;
    *(ushort4*)((unsigned short*)out + ro + CDIM) = lv;
}

// ---------------------------------------------------------------------------
// Split-bf16 + transpose of weights: W fp32 [2048][N] -> out bf16 [N][hi2048|lo2048]
// ---------------------------------------------------------------------------
__global__ void convert_Bt_kernel(const float* __restrict__ W, __nv_bfloat16* __restrict__ out,
                                  int N) {
    __shared__ float t[32][33];
    int k0 = blockIdx.x * 32, n0 = blockIdx.y * 32;
    int tx = threadIdx.x, ty = threadIdx.y;   // (32, 8)
    #pragma unroll
    for (int r = 0; r < 32; r += 8)
        t[ty + r][tx] = W[(size_t)(k0 + ty + r) * N + n0 + tx];
    __syncthreads();
    #pragma unroll
    for (int r = 0; r < 32; r += 8) {
        int n = n0 + ty + r;
        int k = k0 + tx;
        float v = t[tx][ty + r];
        __nv_bfloat16 hi = __float2bfloat16(v);
        __nv_bfloat16 lo = __float2bfloat16(v - __bfloat162float(hi));
        size_t ro = (size_t)n * KP;
        out[ro + k]        = hi;
        out[ro + CDIM + k] = lo;
    }
}

// ---------------------------------------------------------------------------
// mma.sync bf16 GEMM: C = A''@Bt''^T + bias, logical K' = 6144 on [hi|lo] planes:
//   A: physA(i) = i<32 ? i : i-32   ([hi|hi|lo])
//   B: physB(i) = i<64 ? i : i-64   ([hi|lo|hi])
// CTA tile 128x128, BK=64, 3-stage cp.async ring, 4 warps (2Mx2N), warp tile
// 64x64 (raises mma:ldsm byte ratio 192->128 B/mma; smem-crossbar balance).
// ---------------------------------------------------------------------------
#define STAGES 3
#define STAGE_BYTES (32 * 1024)
#define GEMM_SMEM (STAGES * STAGE_BYTES + 1024)

__global__ __launch_bounds__(128, 2)
void mma_gemm_kernel(const __nv_bfloat16* __restrict__ A,
                     const __nv_bfloat16* __restrict__ Bt,
                     const float* __restrict__ bias,
                     float* __restrict__ C, int N) {
    extern __shared__ char smem_raw[];
    uint32_t smem_base = (smem_u32(smem_raw) + 1023u) & ~1023u;

    int tid  = threadIdx.x;
    int wid  = tid >> 5, lane = tid & 31;
    int wm   = wid >> 1;          // 0..1 (M: 64 rows each)
    int wn   = wid & 1;           // 0..1 (N: 64 cols each)

    int n0 = blockIdx.x * 128;
    int m0 = blockIdx.y * 128;

    const __nv_bfloat16* Ag0 = A  + (size_t)m0 * KP;
    const __nv_bfloat16* Bg0 = Bt + (size_t)n0 * KP;

    // ldmatrix per-thread offsets: 4 A-frag rows, 4 B-frag rows (warp 64x64)
    uint32_t a_off[4], a_xor[4];
    #pragma unroll
    for (int mi = 0; mi < 4; mi++) {
        int row = wm * 64 + mi * 16 + (lane & 15);
        a_off[mi] = (uint32_t)row * 128u;
        a_xor[mi] = (uint32_t)((row & 7) << 4);
    }
    uint32_t a_kb = (uint32_t)((lane >> 4) * 16);
    uint32_t b_off[4], b_xor[4];
    #pragma unroll
    for (int ng = 0; ng < 4; ng++) {
        int row = wn * 64 + ng * 16 + ((lane >> 4) << 3) + (lane & 7);
        b_off[ng] = 16384u + (uint32_t)row * 128u;
        b_xor[ng] = (uint32_t)((row & 7) << 4);
    }
    uint32_t b_kb = (uint32_t)(((lane >> 3) & 1) * 16);

    float d[4][8][4];
    #pragma unroll
    for (int mi = 0; mi < 4; mi++)
        #pragma unroll
        for (int ni = 0; ni < 8; ni++)
            #pragma unroll
            for (int c = 0; c < 4; c++) d[mi][ni][c] = 0.f;

    auto fill = [&](int s, int i) {
        int ia = (i < 32) ? i : i - 32;   // A physical chunk
        int ib = (i < 64) ? i : i - 64;   // B physical chunk
        uint32_t st_base = smem_base + s * STAGE_BYTES;
        const __nv_bfloat16* Ag = Ag0 + ia * 64;
        #pragma unroll
        for (int j = 0; j < 8; j++) {
            int ch  = j * 128 + tid;              // 0..1023
            int row = ch >> 3, col = ch & 7;
            uint32_t off = (uint32_t)row * 128u + (uint32_t)col * 16u;
            uint32_t dst = st_base + (off ^ ((off >> 3) & 0x70u));
            CP_ASYNC16(dst, Ag + (size_t)row * KP + col * 8);
        }
        const __nv_bfloat16* Bg = Bg0 + ib * 64;
        #pragma unroll
        for (int j = 0; j < 8; j++) {
            int ch  = j * 128 + tid;
            int row = ch >> 3, col = ch & 7;
            uint32_t off = (uint32_t)row * 128u + (uint32_t)col * 16u;
            uint32_t dst = st_base + 16384u + (off ^ ((off >> 3) & 0x70u));
            CP_ASYNC16(dst, Bg + (size_t)row * KP + col * 8);
        }
    };

    fill(0, 0); CP_COMMIT();
    fill(1, 1); CP_COMMIT();

    for (int i = 0; i < NKITER; i++) {
        int s = i % STAGES;
        CP_WAIT(1);
        __syncthreads();
        if (i + 2 < NKITER) fill((i + 2) % STAGES, i + 2);
        CP_COMMIT();

        uint32_t stb = smem_base + s * STAGE_BYTES;
        #pragma unroll
        for (int ks = 0; ks < 4; ks++) {
            uint32_t kk = (uint32_t)(ks * 32);
            uint32_t af[4][4];
            #pragma unroll
            for (int mi = 0; mi < 4; mi++) {
                uint32_t addr = stb + a_off[mi] + ((kk + a_kb) ^ a_xor[mi]);
                ldsm_x4(af[mi][0], af[mi][1], af[mi][2], af[mi][3], addr);
            }
            uint32_t bf[4][4];
            #pragma unroll
            for (int ng = 0; ng < 4; ng++) {
                uint32_t addr = stb + b_off[ng] + ((kk + b_kb) ^ b_xor[ng]);
                ldsm_x4(bf[ng][0], bf[ng][1], bf[ng][2], bf[ng][3], addr);
            }
            #pragma unroll
            for (int mi = 0; mi < 4; mi++)
                #pragma unroll
                for (int ni = 0; ni < 8; ni++) {
                    int ng = ni >> 1, sub = ni & 1;
                    mma_bf16(d[mi][ni][0], d[mi][ni][1], d[mi][ni][2], d[mi][ni][3],
                             af[mi][0], af[mi][1], af[mi][2], af[mi][3],
                             bf[ng][sub * 2], bf[ng][sub * 2 + 1]);
                }
        }
    }
    CP_WAIT(0);

    int row_base = m0 + wm * 64 + (lane >> 2);
    int col_base = n0 + wn * 64 + (lane & 3) * 2;
    #pragma unroll
    for (int ni = 0; ni < 8; ni++) {
        int col = col_base + ni * 8;
        float2 bs = *(const float2*)(bias + col);
        #pragma unroll
        for (int mi = 0; mi < 4; mi++) {
            int r0 = row_base + mi * 16;
            float2 v0 = { d[mi][ni][0] + bs.x, d[mi][ni][1] + bs.y };
            float2 v1 = { d[mi][ni][2] + bs.x, d[mi][ni][3] + bs.y };
            *(float2*)(C + (size_t)r0 * N + col)       = v0;
            *(float2*)(C + (size_t)(r0 + 8) * N + col) = v1;
        }
    }
}

// ---------------------------------------------------------------------------
// RoPE + split into bf16 hi/lo: qkv -> g_qs (scaled), g_ks  [bh][t][hi128|lo128]
// ---------------------------------------------------------------------------
__global__ void rope_split_kernel(const float* __restrict__ qkv,
                                  const float* __restrict__ ct,
                                  const float* __restrict__ st,
                                  __nv_bfloat16* __restrict__ qs,
                                  __nv_bfloat16* __restrict__ ks) {
    int idx = blockIdx.x * blockDim.x + threadIdx.x;
    if (idx >= BHTOT * SEQ * HDIM) return;
    int d  = idx & 127;
    int t  = (idx >> 7) & 1023;
    int bh = idx >> 17;
    int b  = bh >> 4;
    int h  = bh & 15;
    const float scale = 0.08838834764831845f;  // 1/sqrt(128)

    size_t base = (size_t)(b * SEQ + t) * C3 + h * HDIM;
    int i = d & 63;
    float c = ct[t * 64 + i];
    float s = st[t * 64 + i];
    float q1 = qkv[base + i];
    float q2 = qkv[base + i + 64];
    float k1 = qkv[base + CDIM + i];
    float k2 = qkv[base + CDIM + i + 64];
    float qo, ko;
    if (d < 64) { qo = q1 * c - q2 * s; ko = k1 * c - k2 * s; }
    else        { qo = q1 * s + q2 * c; ko = k1 * s + k2 * c; }
    qo *= scale;

    __nv_bfloat16 qh = __float2bfloat16(qo);
    __nv_bfloat16 ql = __float2bfloat16(qo - __bfloat162float(qh));
    __nv_bfloat16 kh = __float2bfloat16(ko);
    __nv_bfloat16 kl = __float2bfloat16(ko - __bfloat162float(kh));
    size_t ro = ((size_t)bh * SEQ + t) * 256;
    qs[ro + d]       = qh;
    qs[ro + 128 + d] = ql;
    ks[ro + d]       = kh;
    ks[ro + 128 + d] = kl;
}

// ---------------------------------------------------------------------------
// V transpose + split: qkv v-part [b][t][h][d] -> g_vt [bh][d][hi|lo][t]
// ---------------------------------------------------------------------------
__global__ void vt_split_kernel(const float* __restrict__ qkv,
                                __nv_bfloat16* __restrict__ vt) {
    __shared__ float tile[32][33];
    int t0 = blockIdx.x * 32;
    int d0 = blockIdx.y * 32;
    int bh = blockIdx.z;
    int b = bh >> 4, h = bh & 15;
    int tx = threadIdx.x, ty = threadIdx.y;  // (32, 8)
    #pragma unroll
    for (int r = 0; r < 32; r += 8)
        tile[ty + r][tx] = qkv[(size_t)(b * SEQ + t0 + ty + r) * C3 + 2 * CDIM + h * HDIM + d0 + tx];
    __syncthreads();
    #pragma unroll
    for (int r = 0; r < 32; r += 8) {
        int d = d0 + ty + r;
        int t = t0 + tx;
        float v = tile[tx][ty + r];
        __nv_bfloat16 hi = __float2bfloat16(v);
        __nv_bfloat16 lo = __float2bfloat16(v - __bfloat162float(hi));
        size_t base = (((size_t)bh * HDIM + d) * 2) * SEQ + t;
        vt[base]       = hi;
        vt[base + SEQ] = lo;
    }
}

// ---------------------------------------------------------------------------
// Tensor-core flash attention, split-bf16, causal.
// CTA: 64 q rows (one bh), 4 warps x 16 rows x full 32-col k-tile.
// ---------------------------------------------------------------------------
#define FA_SMEM (32768 + 2 * 32768 + 128)

__global__ __launch_bounds__(128, 2)
void flash_mma_kernel(const __nv_bfloat16* __restrict__ qs,
                      const __nv_bfloat16* __restrict__ ks,
                      const __nv_bfloat16* __restrict__ vt,
                      float* __restrict__ Y) {
    extern __shared__ char smraw[];
    uint32_t smQ = (smem_u32(smraw) + 127u) & ~127u;

    int tid  = threadIdx.x;
    int wid  = tid >> 5, lane = tid & 31;
    int qt   = blockIdx.x;
    int bh   = blockIdx.y;
    int q0   = qt * 64;
    int b = bh >> 4, h = bh & 15;

    const __nv_bfloat16* Qg = qs + ((size_t)bh * SEQ + q0) * 256;
    #pragma unroll
    for (int j = 0; j < 16; j++) {
        int ch = j * 128 + tid;
        int row = ch >> 5, c16 = ch & 31;
        uint32_t dst = smQ + (uint32_t)row * 512u + (uint32_t)((c16 ^ (row & 7)) << 4);
        CP_ASYNC16(dst, Qg + (size_t)row * 256 + c16 * 8);
    }

    auto fillKV = [&](int s, int kt) {
        int k0 = kt * 32;
        uint32_t smK = smQ + 32768u + (uint32_t)s * 32768u;
        uint32_t smV = smK + 16384u;
        const __nv_bfloat16* Kg = ks + ((size_t)bh * SEQ + k0) * 256;
        #pragma unroll
        for (int j = 0; j < 8; j++) {
            int ch = j * 128 + tid;
            int row = ch >> 5, c16 = ch & 31;
            uint32_t dst = smK + (uint32_t)row * 512u + (uint32_t)((c16 ^ (row & 7)) << 4);
            CP_ASYNC16(dst, Kg + (size_t)row * 256 + c16 * 8);
        }
        const __nv_bfloat16* Vg = vt + (size_t)bh * HDIM * 2 * SEQ + k0;
        #pragma unroll
        for (int j = 0; j < 8; j++) {
            int ch = j * 128 + tid;
            int row = ch >> 3, c16 = ch & 7;
            int plane = c16 >> 2, tc = c16 & 3;
            uint32_t dst = smV + (uint32_t)row * 128u + (uint32_t)((c16 ^ (row & 7)) << 4);
            CP_ASYNC16(dst, Vg + ((size_t)row * 2 + plane) * SEQ + tc * 8);
        }
    };

    fillKV(0, 0);
    CP_COMMIT();

    float O[16][4];
    #pragma unroll
    for (int nf = 0; nf < 16; nf++)
        #pragma unroll
        for (int c = 0; c < 4; c++) O[nf][c] = 0.f;
    float mrow[2] = { -1e30f, -1e30f };
    float lrow[2] = { 0.f, 0.f };

    int arow = wid * 16 + (lane & 15);
    uint32_t a_base = (uint32_t)arow * 512u;
    uint32_t a_x7   = (uint32_t)(arow & 7) << 4;
    uint32_t a_kb   = (uint32_t)((lane >> 4) << 4);
    int b_sub = ((lane >> 4) << 3) + (lane & 7);
    uint32_t b_kb = (uint32_t)(((lane >> 3) & 1) << 4);

    int nkt = 2 * qt + 2;
    for (int kt = 0; kt < nkt; kt++) {
        if (kt + 1 < nkt) { fillKV((kt + 1) & 1, kt + 1); CP_COMMIT(); CP_WAIT(1); }
        else              { CP_WAIT(0); }
        __syncthreads();

        uint32_t smK = smQ + 32768u + (uint32_t)(kt & 1) * 32768u;
        uint32_t smV = smK + 16384u;

        float S[4][4];
        #pragma unroll
        for (int ni = 0; ni < 4; ni++)
            #pragma unroll
            for (int c = 0; c < 4; c++) S[ni][c] = 0.f;

        #pragma unroll
        for (int p = 0; p < 3; p++) {
            uint32_t qoff = (p == 2) ? 256u : 0u;
            uint32_t koff = (p == 1) ? 256u : 0u;
            #pragma unroll
            for (int kd = 0; kd < 8; kd++) {
                uint32_t a[4];
                ldsm_x4(a[0], a[1], a[2], a[3],
                        smQ + a_base + ((qoff + kd * 32 + a_kb) ^ a_x7));
                #pragma unroll
                for (int g = 0; g < 2; g++) {
                    int brow = g * 16 + b_sub;
                    uint32_t bf[4];
                    ldsm_x4(bf[0], bf[1], bf[2], bf[3],
                            smK + (uint32_t)brow * 512u +
                            ((koff + kd * 32 + b_kb) ^ ((uint32_t)(brow & 7) << 4)));
                    #pragma unroll
                    for (int sub = 0; sub < 2; sub++)
                        mma_bf16(S[g*2+sub][0], S[g*2+sub][1], S[g*2+sub][2], S[g*2+sub][3],
                                 a[0], a[1], a[2], a[3], bf[sub*2], bf[sub*2+1]);
                }
            }
        }

        if (kt >= 2 * qt) {
            int k0 = kt * 32;
            #pragma unroll
            for (int ni = 0; ni < 4; ni++) {
                #pragma unroll
                for (int c = 0; c < 4; c++) {
                    int gr = q0 + wid * 16 + (lane >> 2) + ((c >> 1) << 3);
                    int gc = k0 + ni * 8 + (lane & 3) * 2 + (c & 1);
                    if (gc > gr) S[ni][c] = -1e30f;
                }
            }
        }

        uint32_t phi[2][4], plo[2][4];
        #pragma unroll
        for (int i = 0; i < 2; i++) {
            float vmax = -1e30f;
            #pragma unroll
            for (int ni = 0; ni < 4; ni++)
                vmax = fmaxf(vmax, fmaxf(S[ni][2*i], S[ni][2*i+1]));
            vmax = fmaxf(vmax, __shfl_xor_sync(0xffffffffu, vmax, 1));
            vmax = fmaxf(vmax, __shfl_xor_sync(0xffffffffu, vmax, 2));
            float mnew  = fmaxf(mrow[i], vmax);
            float alpha = __expf(mrow[i] - mnew);
            mrow[i] = mnew;
            float rs = 0.f;
            #pragma unroll
            for (int ni = 0; ni < 4; ni++) {
                float p0 = __expf(S[ni][2*i]   - mnew);
                float p1 = __expf(S[ni][2*i+1] - mnew);
                S[ni][2*i] = p0; S[ni][2*i+1] = p1;
                rs += p0 + p1;
            }
            rs += __shfl_xor_sync(0xffffffffu, rs, 1);
            rs += __shfl_xor_sync(0xffffffffu, rs, 2);
            lrow[i] = lrow[i] * alpha + rs;
            #pragma unroll
            for (int nf = 0; nf < 16; nf++) {
                O[nf][2*i]   *= alpha;
                O[nf][2*i+1] *= alpha;
            }
        }
        #pragma unroll
        for (int ks2 = 0; ks2 < 2; ks2++) {
            #pragma unroll
            for (int half = 0; half < 2; half++) {
                int ni = 2 * ks2 + half;
                float p00 = S[ni][0], p01 = S[ni][1], p10 = S[ni][2], p11 = S[ni][3];
                __nv_bfloat16 h00 = __float2bfloat16(p00), h01 = __float2bfloat16(p01);
                __nv_bfloat16 h10 = __float2bfloat16(p10), h11 = __float2bfloat16(p11);
                phi[ks2][half*2+0] = pack_bf16(__bfloat162float(h00), __bfloat162float(h01));
                phi[ks2][half*2+1] = pack_bf16(__bfloat162float(h10), __bfloat162float(h11));
                plo[ks2][half*2+0] = pack_bf16(p00 - __bfloat162float(h00),
                                               p01 - __bfloat162float(h01));
                plo[ks2][half*2+1] = pack_bf16(p10 - __bfloat162float(h10),
                                               p11 - __bfloat162float(h11));
            }
        }

        #pragma unroll
        for (int p = 0; p < 3; p++) {
            uint32_t (*A)[4] = (p == 2) ? plo : phi;
            uint32_t voff = (p == 1) ? 64u : 0u;
            #pragma unroll
            for (int ks2 = 0; ks2 < 2; ks2++) {
                uint32_t koffb = voff + ks2 * 32;
                #pragma unroll
                for (int nb = 0; nb < 8; nb++) {
                    int brow = nb * 16 + b_sub;
                    uint32_t bv[4];
                    ldsm_x4(bv[0], bv[1], bv[2], bv[3],
                            smV + (uint32_t)brow * 128u +
                            ((koffb + b_kb) ^ ((uint32_t)(brow & 7) << 4)));
                    #pragma unroll
                    for (int sub = 0; sub < 2; sub++) {
                        int nf = nb * 2 + sub;
                        mma_bf16(O[nf][0], O[nf][1], O[nf][2], O[nf][3],
                                 A[ks2][0], A[ks2][1], A[ks2][2], A[ks2][3],
                                 bv[sub*2], bv[sub*2+1]);
                    }
                }
            }
        }
        __syncthreads();
    }

    #pragma unroll
    for (int i = 0; i < 2; i++) {
        float inv = 1.0f / lrow[i];
        int trow = q0 + wid * 16 + (lane >> 2) + 8 * i;
        float* yr = Y + (size_t)(b * SEQ + trow) * CDIM + h * HDIM + (lane & 3) * 2;
        #pragma unroll
        for (int nf = 0; nf < 16; nf++) {
            float2 v = { O[nf][2*i] * inv, O[nf][2*i+1] * inv };
            *(float2*)(yr + nf * 8) = v;
        }
    }
}

// ---------------------------------------------------------------------------
extern "C" void kernel_launch(void* const* d_in, const int* in_sizes, int n_in,
                              void* d_out, int out_size) {
    const float* x      = (const float*)d_in[0];
    const float* w_attn = (const float*)d_in[1];
    const float* b_attn = (const float*)d_in[2];
    const float* w_proj = (const float*)d_in[3];
    const float* b_proj = (const float*)d_in[4];
    float* out = (float*)d_out;

    float *qkv, *y, *ct, *st;
    __nv_bfloat16 *Abuf, *Bt1, *Bt2, *qsb, *ksb, *vtb;
    cudaGetSymbolAddress((void**)&qkv,  g_qkv);
    cudaGetSymbolAddress((void**)&y,    g_y);
    cudaGetSymbolAddress((void**)&ct,   g_cos);
    cudaGetSymbolAddress((void**)&st,   g_sin);
    cudaGetSymbolAddress((void**)&Abuf, g_Abuf);
    cudaGetSymbolAddress((void**)&Bt1,  g_Bt1);
    cudaGetSymbolAddress((void**)&Bt2,  g_Bt2);
    cudaGetSymbolAddress((void**)&qsb,  g_qs);
    cudaGetSymbolAddress((void**)&ksb,  g_ks);
    cudaGetSymbolAddress((void**)&vtb,  g_vt);

    cudaFuncSetAttribute(mma_gemm_kernel,
                         cudaFuncAttributeMaxDynamicSharedMemorySize, GEMM_SMEM);
    cudaFuncSetAttribute(flash_mma_kernel,
                         cudaFuncAttributeMaxDynamicSharedMemorySize, FA_SMEM);

    // RoPE tables
    build_rope_kernel<<<(SEQ * 64 + 255) / 256, 256>>>(ct, st);

    // Split-bf16 conversions for QKV GEMM
    convert_A_kernel<<<(MROWS * CDIM / 4 + 255) / 256, 256>>>(x, Abuf);
    convert_Bt_kernel<<<dim3(CDIM / 32, C3 / 32), dim3(32, 8)>>>(w_attn, Bt1, C3);

    // QKV projection (HMMA, 128 threads / 4 warps per CTA)
    mma_gemm_kernel<<<dim3(C3 / 128, MROWS / 128), 128, GEMM_SMEM>>>(
        Abuf, Bt1, b_attn, qkv, C3);

    // RoPE + split into bf16 hi/lo; V transpose + split
    rope_split_kernel<<<(BHTOT * SEQ * HDIM + 255) / 256, 256>>>(qkv, ct, st, qsb, ksb);
    vt_split_kernel<<<dim3(SEQ / 32, HDIM / 32, BHTOT), dim3(32, 8)>>>(qkv, vtb);

    // Tensor-core flash attention -> y
    flash_mma_kernel<<<dim3(SEQ / 64, BHTOT), 128, FA_SMEM>>>(qsb, ksb, vtb, y);

    // Split-bf16 conversions for output projection
    convert_A_kernel<<<(MROWS * CDIM / 4 + 255) / 256, 256>>>(y, Abuf);
    convert_Bt_kernel<<<dim3(CDIM / 32, CDIM / 32), dim3(32, 8)>>>(w_proj, Bt2, CDIM);

    // Output projection (HMMA) -> d_out
    mma_gemm_kernel<<<dim3(CDIM / 128, MROWS / 128), 128, GEMM_SMEM>>>(
        Abuf, Bt2, b_proj, out, CDIM);
}